// round 2
// baseline (speedup 1.0000x reference)
#include <cuda_runtime.h>
#include <cuda_bf16.h>
#include <math.h>

// Problem constants
#define BB 4
#define TT 512
#define DD 2048
#define HH 6
#define KK 256
#define VV 512
#define NHH 2
#define NTOK (BB * TT)          // 2048
#define KEY_DIM (HH * KK)       // 1536
#define VAL_DIM (HH * VV)       // 3072

// ---------------- scratch (static device globals; no allocation) -------------
__device__ float d_qbuf[NTOK * KEY_DIM];          // [B,T,H,K]  silu(q)
__device__ float d_kbuf[NTOK * KEY_DIM * NHH];    // [B,T,NH,H,K] silu(k) -> normalized in place
__device__ float d_vbuf[NTOK * VAL_DIM * NHH];    // [B,T,NH,H,V] silu(v)
__device__ float d_gatebuf[NTOK * VAL_DIM];       // raw x@Wg^T
__device__ float d_betabuf[NTOK * NHH * HH];      // [B,T,NH,H]
__device__ float d_gbuf[NTOK * HH];               // [B,T,H]
__device__ float d_omid[NTOK * VAL_DIM];          // [B,T,H,V] recurrence out -> normed in place

// ---------------- fp32 SIMT GEMM: C[m,n] = act(sum_k A[m,k] * B[n,k]) --------
#define BM 128
#define BN 128
#define BKD 16

__global__ void __launch_bounds__(256) gemm_nt(const float* __restrict__ A,
                                               const float* __restrict__ Bw,
                                               float* __restrict__ C,
                                               int M, int N, int Kd, int act) {
    __shared__ float As[BKD][BM + 4];
    __shared__ float Bs[BKD][BN + 4];
    const int tid = threadIdx.x;
    const int tx = tid & 15;
    const int ty = tid >> 4;
    const int m0 = blockIdx.y * BM;
    const int n0 = blockIdx.x * BN;
    const int lrow = tid >> 2;        // 0..63
    const int lcol = (tid & 3) << 2;  // 0,4,8,12

    float acc[8][8];
#pragma unroll
    for (int i = 0; i < 8; i++)
#pragma unroll
        for (int j = 0; j < 8; j++) acc[i][j] = 0.f;

    for (int k0 = 0; k0 < Kd; k0 += BKD) {
#pragma unroll
        for (int jj = 0; jj < 2; jj++) {
            int r = lrow + jj * 64;
            float4 ta = *(const float4*)(A + (size_t)(m0 + r) * Kd + k0 + lcol);
            As[lcol + 0][r] = ta.x;
            As[lcol + 1][r] = ta.y;
            As[lcol + 2][r] = ta.z;
            As[lcol + 3][r] = ta.w;
            float4 tb = *(const float4*)(Bw + (size_t)(n0 + r) * Kd + k0 + lcol);
            Bs[lcol + 0][r] = tb.x;
            Bs[lcol + 1][r] = tb.y;
            Bs[lcol + 2][r] = tb.z;
            Bs[lcol + 3][r] = tb.w;
        }
        __syncthreads();
#pragma unroll
        for (int kk = 0; kk < BKD; kk++) {
            float ar[8], br[8];
#pragma unroll
            for (int i = 0; i < 8; i++) ar[i] = As[kk][ty * 8 + i];
#pragma unroll
            for (int j = 0; j < 8; j++) br[j] = Bs[kk][tx * 8 + j];
#pragma unroll
            for (int i = 0; i < 8; i++)
#pragma unroll
                for (int j = 0; j < 8; j++) acc[i][j] = fmaf(ar[i], br[j], acc[i][j]);
        }
        __syncthreads();
    }
#pragma unroll
    for (int i = 0; i < 8; i++) {
        int m = m0 + ty * 8 + i;
#pragma unroll
        for (int j = 0; j < 8; j++) {
            int n = n0 + tx * 8 + j;
            float v = acc[i][j];
            if (act == 1) v = v / (1.f + expf(-v));  // silu
            C[(size_t)m * N + n] = v;
        }
    }
}

// ------------- small projections: beta (12 outs) and g (6 outs) per token ----
__global__ void __launch_bounds__(256) proj_small(const float* __restrict__ x,
                                                  const float* __restrict__ Wb,
                                                  const float* __restrict__ Wa,
                                                  const float* __restrict__ A_log,
                                                  const float* __restrict__ dt_bias) {
    int warp = (blockIdx.x * blockDim.x + threadIdx.x) >> 5;  // 0 .. 2048*18-1
    int l = threadIdx.x & 31;
    int t = warp / 18;
    int o = warp % 18;
    const float* xr = x + (size_t)t * DD;
    const float* wr = (o < 12) ? (Wb + (size_t)o * DD) : (Wa + (size_t)(o - 12) * DD);
    float s = 0.f;
    for (int i = l; i < DD; i += 32) s = fmaf(xr[i], wr[i], s);
#pragma unroll
    for (int off = 16; off > 0; off >>= 1) s += __shfl_xor_sync(0xffffffffu, s, off);
    if (l == 0) {
        if (o < 12) {
            d_betabuf[(size_t)t * 12 + o] = 2.f / (1.f + expf(-s));
        } else {
            int h = o - 12;
            float z = s + dt_bias[h];
            float sp = (z > 20.f) ? z : log1pf(expf(z));
            d_gbuf[(size_t)t * 6 + h] = -expf(A_log[h]) * sp;
        }
    }
}

// ------------- normalize k rows (length 256) in place ------------------------
__global__ void __launch_bounds__(256) knorm_kernel() {
    int warp = (blockIdx.x * blockDim.x + threadIdx.x) >> 5;  // 0 .. 24575
    int l = threadIdx.x & 31;
    float* row = d_kbuf + (size_t)warp * KK;
    float vr[8];
    float s = 0.f;
#pragma unroll
    for (int i = 0; i < 8; i++) {
        vr[i] = row[l + 32 * i];
        s = fmaf(vr[i], vr[i], s);
    }
#pragma unroll
    for (int off = 16; off > 0; off >>= 1) s += __shfl_xor_sync(0xffffffffu, s, off);
    float inv = 1.f / fmaxf(sqrtf(s), 1e-12f);
#pragma unroll
    for (int i = 0; i < 8; i++) row[l + 32 * i] = vr[i] * inv;
}

// ------------- recurrence: 96 persistent CTAs, state in registers ------------
// CTA = (bh, vchunk): bh in 0..23, vchunk in 0..3 (128 v columns each).
// Warp w owns v columns [vchunk*128 + w*16, +16); lane l owns k = l + 32*i.
__global__ void __launch_bounds__(256, 1) recurrence_kernel() {
    const int cta = blockIdx.x;
    const int bh = cta >> 2;
    const int vc = cta & 3;
    const int b = bh / HH;
    const int h = bh % HH;
    const int w = threadIdx.x >> 5;
    const int l = threadIdx.x & 31;
    const int vbase = vc * 128 + w * 16;

    float hst[8][16];
#pragma unroll
    for (int i = 0; i < 8; i++)
#pragma unroll
        for (int c = 0; c < 16; c++) hst[i][c] = 0.f;

    const float scale = 0.0625f;  // 256^-0.5

    for (int t = 0; t < TT; t++) {
        const size_t tb = (size_t)b * TT + t;
        const float* qp = d_qbuf + tb * KEY_DIM + h * KK;
        const float* k0p = d_kbuf + tb * (KEY_DIM * NHH) + h * KK;
        const float* k1p = k0p + HH * KK;
        const float* v0p = d_vbuf + tb * (VAL_DIM * NHH) + h * VV + vbase;
        const float* v1p = v0p + HH * VV;
        float gt = d_gbuf[tb * HH + h];
        float b0 = d_betabuf[tb * 12 + h];
        float b1 = d_betabuf[tb * 12 + 6 + h];
        float eg = expf(gt);

        float qs[8], a0[8], a1[8];
#pragma unroll
        for (int i = 0; i < 8; i++) {
            int kk = l + 32 * i;
            qs[i] = qp[kk] * scale;
            a0[i] = k0p[kk];
            a1[i] = k1p[kk];
        }
        float vv0[16], vv1[16];
#pragma unroll
        for (int c = 0; c < 16; c++) {
            vv0[c] = v0p[c];
            vv1[c] = v1p[c];
        }

        float acc[16];
        // pass 1: decay + pred0
#pragma unroll
        for (int c = 0; c < 16; c++) acc[c] = 0.f;
#pragma unroll
        for (int i = 0; i < 8; i++)
#pragma unroll
            for (int c = 0; c < 16; c++) {
                hst[i][c] *= eg;
                acc[c] = fmaf(hst[i][c], a0[i], acc[c]);
            }
#pragma unroll
        for (int c = 0; c < 16; c++)
#pragma unroll
            for (int off = 16; off > 0; off >>= 1)
                acc[c] += __shfl_xor_sync(0xffffffffu, acc[c], off);
#pragma unroll
        for (int c = 0; c < 16; c++) vv0[c] -= acc[c];  // delta0
#pragma unroll
        for (int i = 0; i < 8; i++) a0[i] *= b0;        // beta0 * kn0

        // pass 2: update0 + pred1
#pragma unroll
        for (int c = 0; c < 16; c++) acc[c] = 0.f;
#pragma unroll
        for (int i = 0; i < 8; i++)
#pragma unroll
            for (int c = 0; c < 16; c++) {
                hst[i][c] = fmaf(a0[i], vv0[c], hst[i][c]);
                acc[c] = fmaf(hst[i][c], a1[i], acc[c]);
            }
#pragma unroll
        for (int c = 0; c < 16; c++)
#pragma unroll
            for (int off = 16; off > 0; off >>= 1)
                acc[c] += __shfl_xor_sync(0xffffffffu, acc[c], off);
#pragma unroll
        for (int c = 0; c < 16; c++) vv1[c] -= acc[c];  // delta1
#pragma unroll
        for (int i = 0; i < 8; i++) a1[i] *= b1;        // beta1 * kn1

        // pass 3: update1 + output
#pragma unroll
        for (int c = 0; c < 16; c++) acc[c] = 0.f;
#pragma unroll
        for (int i = 0; i < 8; i++)
#pragma unroll
            for (int c = 0; c < 16; c++) {
                hst[i][c] = fmaf(a1[i], vv1[c], hst[i][c]);
                acc[c] = fmaf(hst[i][c], qs[i], acc[c]);
            }
#pragma unroll
        for (int c = 0; c < 16; c++)
#pragma unroll
            for (int off = 16; off > 0; off >>= 1)
                acc[c] += __shfl_xor_sync(0xffffffffu, acc[c], off);

        float* op = d_omid + tb * VAL_DIM + h * VV + vbase;
#pragma unroll
        for (int c = 0; c < 16; c++)
            if (l == c) op[c] = acc[c];
    }
}

// ------------- gated RMSNorm over V=512, in place on d_omid ------------------
__global__ void __launch_bounds__(256) rmsgate_kernel(const float* __restrict__ wnorm) {
    int warp = (blockIdx.x * blockDim.x + threadIdx.x) >> 5;  // row: 0..12287 = (b,t,h)
    int l = threadIdx.x & 31;
    float* row = d_omid + (size_t)warp * VV;
    const float* gr = d_gatebuf + (size_t)warp * VV;
    float vr[16];
    float s = 0.f;
#pragma unroll
    for (int i = 0; i < 16; i++) {
        vr[i] = row[l + 32 * i];
        s = fmaf(vr[i], vr[i], s);
    }
#pragma unroll
    for (int off = 16; off > 0; off >>= 1) s += __shfl_xor_sync(0xffffffffu, s, off);
    float rinv = rsqrtf(s * (1.f / (float)VV) + 1e-5f);
#pragma unroll
    for (int i = 0; i < 16; i++) {
        int idx = l + 32 * i;
        float gv = gr[idx];
        float sig = 1.f / (1.f + expf(-gv));
        row[idx] = vr[i] * rinv * wnorm[idx] * sig;
    }
}

// ---------------------------------------------------------------------------
extern "C" void kernel_launch(void* const* d_in, const int* in_sizes, int n_in,
                              void* d_out, int out_size) {
    const float* x = (const float*)d_in[0];
    const float* Wq = (const float*)d_in[1];
    const float* Wk = (const float*)d_in[2];
    const float* Wv = (const float*)d_in[3];
    const float* Wb = (const float*)d_in[4];
    const float* Wa = (const float*)d_in[5];
    const float* A_log = (const float*)d_in[6];
    const float* dt_bias = (const float*)d_in[7];
    const float* Wg = (const float*)d_in[8];
    const float* Wo = (const float*)d_in[9];
    const float* o_norm_w = (const float*)d_in[10];
    float* out = (float*)d_out;

    float* qbuf;    cudaGetSymbolAddress((void**)&qbuf, d_qbuf);
    float* kbuf;    cudaGetSymbolAddress((void**)&kbuf, d_kbuf);
    float* vbuf;    cudaGetSymbolAddress((void**)&vbuf, d_vbuf);
    float* gatebuf; cudaGetSymbolAddress((void**)&gatebuf, d_gatebuf);
    float* omid;    cudaGetSymbolAddress((void**)&omid, d_omid);

    // Projections (fused SiLU where needed)
    gemm_nt<<<dim3(KEY_DIM / BN, NTOK / BM), 256>>>(x, Wq, qbuf, NTOK, KEY_DIM, DD, 1);
    gemm_nt<<<dim3(KEY_DIM * NHH / BN, NTOK / BM), 256>>>(x, Wk, kbuf, NTOK, KEY_DIM * NHH, DD, 1);
    gemm_nt<<<dim3(VAL_DIM * NHH / BN, NTOK / BM), 256>>>(x, Wv, vbuf, NTOK, VAL_DIM * NHH, DD, 1);
    gemm_nt<<<dim3(VAL_DIM / BN, NTOK / BM), 256>>>(x, Wg, gatebuf, NTOK, VAL_DIM, DD, 0);

    // beta / g (18 tiny outputs per token)
    proj_small<<<(NTOK * 18) / 8, 256>>>(x, Wb, Wa, A_log, dt_bias);

    // normalize k rows
    knorm_kernel<<<(NTOK * NHH * HH) / 8, 256>>>();

    // sequential recurrence (persistent, state in registers)
    recurrence_kernel<<<96, 256>>>();

    // gated RMSNorm
    rmsgate_kernel<<<(NTOK * HH) / 8, 256>>>(o_norm_w);

    // output projection
    gemm_nt<<<dim3(DD / BN, NTOK / BM), 256>>>(omid, Wo, out, NTOK, DD, VAL_DIM, 0);
}

// round 5
// speedup vs baseline: 1.5225x; 1.5225x over previous
#include <cuda_runtime.h>
#include <cuda_bf16.h>
#include <math.h>
#include <stdint.h>

// Problem constants
#define BB 4
#define TT 512
#define DD 2048
#define HH 6
#define KK 256
#define VV 512
#define NHH 2
#define NTOK (BB * TT)          // 2048
#define KEY_DIM (HH * KK)       // 1536
#define VAL_DIM (HH * VV)       // 3072

// ---------------- scratch (static device globals; no allocation) -------------
__device__ float d_qbuf[NTOK * KEY_DIM];
__device__ float d_kbuf[NTOK * KEY_DIM * NHH];
__device__ float d_vbuf[NTOK * VAL_DIM * NHH];
__device__ float d_gatebuf[NTOK * VAL_DIM];
__device__ float d_betabuf[NTOK * NHH * HH];
__device__ float d_gbuf[NTOK * HH];
__device__ float d_omid[NTOK * VAL_DIM];

// bf16 split buffers (hi/lo)
__device__ __nv_bfloat16 d_xhi[NTOK * DD],  d_xlo[NTOK * DD];
__device__ __nv_bfloat16 d_wqhi[KEY_DIM * DD], d_wqlo[KEY_DIM * DD];
__device__ __nv_bfloat16 d_wkhi[KEY_DIM * NHH * DD], d_wklo[KEY_DIM * NHH * DD];
__device__ __nv_bfloat16 d_wvhi[VAL_DIM * NHH * DD], d_wvlo[VAL_DIM * NHH * DD];
__device__ __nv_bfloat16 d_wghi[VAL_DIM * DD], d_wglo[VAL_DIM * DD];
__device__ __nv_bfloat16 d_wohi[DD * VAL_DIM], d_wolo[DD * VAL_DIM];
__device__ __nv_bfloat16 d_onhi[NTOK * VAL_DIM], d_onlo[NTOK * VAL_DIM];

// =================== helpers =================================================
#define CP_ASYNC16(dst, src) \
    asm volatile("cp.async.cg.shared.global [%0], [%1], 16;" :: "r"(dst), "l"(src))
#define CP_COMMIT() asm volatile("cp.async.commit_group;" ::: "memory")

__device__ __forceinline__ uint32_t smem_u32(const void* p) {
    uint32_t a;
    asm("{ .reg .u64 t; cvta.to.shared.u64 t, %1; cvt.u32.u64 %0, t; }" : "=r"(a) : "l"(p));
    return a;
}

__device__ __forceinline__ void mma16816(float* c, const uint32_t* a, const uint32_t* b) {
    asm volatile(
        "mma.sync.aligned.m16n8k16.row.col.f32.bf16.bf16.f32 "
        "{%0,%1,%2,%3}, {%4,%5,%6,%7}, {%8,%9}, {%0,%1,%2,%3};"
        : "+f"(c[0]), "+f"(c[1]), "+f"(c[2]), "+f"(c[3])
        : "r"(a[0]), "r"(a[1]), "r"(a[2]), "r"(a[3]), "r"(b[0]), "r"(b[1]));
}

// =================== fp32 -> bf16 hi/lo split ================================
__global__ void __launch_bounds__(256) split_bf16(const float4* __restrict__ src,
                                                  __nv_bfloat162* __restrict__ hi,
                                                  __nv_bfloat162* __restrict__ lo,
                                                  int n4) {
    int i = blockIdx.x * blockDim.x + threadIdx.x;
    if (i >= n4) return;
    float4 a = src[i];
    __nv_bfloat16 h0 = __float2bfloat16(a.x);
    __nv_bfloat16 h1 = __float2bfloat16(a.y);
    __nv_bfloat16 h2 = __float2bfloat16(a.z);
    __nv_bfloat16 h3 = __float2bfloat16(a.w);
    hi[2 * i + 0] = __nv_bfloat162(h0, h1);
    hi[2 * i + 1] = __nv_bfloat162(h2, h3);
    lo[2 * i + 0] = __nv_bfloat162(__float2bfloat16(a.x - __bfloat162float(h0)),
                                   __float2bfloat16(a.y - __bfloat162float(h1)));
    lo[2 * i + 1] = __nv_bfloat162(__float2bfloat16(a.z - __bfloat162float(h2)),
                                   __float2bfloat16(a.w - __bfloat162float(h3)));
}

// =================== mma.sync bf16 GEMM: C = act(A @ B^T) ====================
// A [M,Kd] hi/lo bf16, B [N,Kd] hi/lo bf16, C [M,N] fp32.
// Tile 128x128, BK=32, 8 warps (2x4), warp tile 64x32.
// 3-term split: D += Ah*Bh + Ah*Bl + Al*Bh.
#define GBM 128
#define GBN 128
#define GBK 32
#define ROWB 80                       // padded row stride bytes (32 bf16 data + 8 pad)
#define TILE_B (128 * ROWB)           // 10240 bytes per tile
#define OFF_AHI 0
#define OFF_ALO TILE_B
#define OFF_BHI (2 * TILE_B)
#define OFF_BLO (3 * TILE_B)
#define STAGE_B (4 * TILE_B)          // 40960
#define GEMM_SMEM (2 * STAGE_B)       // 81920

__global__ void __launch_bounds__(256, 1) gemm_tc(
    const __nv_bfloat16* __restrict__ Ahi, const __nv_bfloat16* __restrict__ Alo,
    const __nv_bfloat16* __restrict__ Bhi, const __nv_bfloat16* __restrict__ Blo,
    float* __restrict__ C, int Kd, int N, int act)
{
    extern __shared__ __align__(128) char smem[];
    const uint32_t sb = smem_u32(smem);
    const int tid = threadIdx.x;
    const int lane = tid & 31;
    const int wid = tid >> 5;
    const int wm = wid >> 2;          // 0..1 : 64-row slab
    const int wn = wid & 3;           // 0..3 : 32-col slab
    const int g = lane >> 2;          // 0..7
    const int q4 = (lane & 3) << 2;   // byte offset within 8 bf16
    const int m0 = blockIdx.y * GBM;
    const int n0 = blockIdx.x * GBN;
    const int NS = Kd / GBK;

    // loader mapping: 8 chunks of 16B per thread per stage
    auto load_stage = [&](int s, int buf) {
        const uint32_t base = sb + buf * STAGE_B;
        const int k0 = s * GBK;
#pragma unroll
        for (int i = 0; i < 8; i++) {
            int c = tid + i * 256;        // 0..2047
            int tile = c >> 9;            // 0..3
            int idx = c & 511;
            int row = idx >> 2;
            int kc = idx & 3;
            uint32_t dst = base + tile * TILE_B + row * ROWB + kc * 16;
            const __nv_bfloat16* srcp;
            if (tile == 0)      srcp = Ahi + (size_t)(m0 + row) * Kd + k0 + kc * 8;
            else if (tile == 1) srcp = Alo + (size_t)(m0 + row) * Kd + k0 + kc * 8;
            else if (tile == 2) srcp = Bhi + (size_t)(n0 + row) * Kd + k0 + kc * 8;
            else                srcp = Blo + (size_t)(n0 + row) * Kd + k0 + kc * 8;
            CP_ASYNC16(dst, (const char*)srcp);
        }
        CP_COMMIT();
    };

    float acc[4][4][4];
#pragma unroll
    for (int mi = 0; mi < 4; mi++)
#pragma unroll
        for (int ni = 0; ni < 4; ni++)
#pragma unroll
            for (int r = 0; r < 4; r++) acc[mi][ni][r] = 0.f;

    load_stage(0, 0);

    for (int s = 0; s < NS; s++) {
        const int buf = s & 1;
        if (s + 1 < NS) {
            load_stage(s + 1, buf ^ 1);
            asm volatile("cp.async.wait_group 1;" ::: "memory");
        } else {
            asm volatile("cp.async.wait_group 0;" ::: "memory");
        }
        __syncthreads();

        const char* st = smem + buf * STAGE_B;
#pragma unroll
        for (int ks = 0; ks < 2; ks++) {
            const int kb = ks * 32 + q4;
            uint32_t ah[4][4], al[4][4], bh[4][2], bl[4][2];
#pragma unroll
            for (int mi = 0; mi < 4; mi++) {
                const char* p = st + OFF_AHI + (wm * 64 + mi * 16 + g) * ROWB + kb;
                ah[mi][0] = *(const uint32_t*)p;
                ah[mi][1] = *(const uint32_t*)(p + 8 * ROWB);
                ah[mi][2] = *(const uint32_t*)(p + 16);
                ah[mi][3] = *(const uint32_t*)(p + 8 * ROWB + 16);
            }
#pragma unroll
            for (int ni = 0; ni < 4; ni++) {
                const char* p = st + OFF_BHI + (wn * 32 + ni * 8 + g) * ROWB + kb;
                bh[ni][0] = *(const uint32_t*)p;
                bh[ni][1] = *(const uint32_t*)(p + 16);
            }
#pragma unroll
            for (int mi = 0; mi < 4; mi++)
#pragma unroll
                for (int ni = 0; ni < 4; ni++) mma16816(acc[mi][ni], ah[mi], bh[ni]);

#pragma unroll
            for (int ni = 0; ni < 4; ni++) {
                const char* p = st + OFF_BLO + (wn * 32 + ni * 8 + g) * ROWB + kb;
                bl[ni][0] = *(const uint32_t*)p;
                bl[ni][1] = *(const uint32_t*)(p + 16);
            }
#pragma unroll
            for (int mi = 0; mi < 4; mi++)
#pragma unroll
                for (int ni = 0; ni < 4; ni++) mma16816(acc[mi][ni], ah[mi], bl[ni]);

#pragma unroll
            for (int mi = 0; mi < 4; mi++) {
                const char* p = st + OFF_ALO + (wm * 64 + mi * 16 + g) * ROWB + kb;
                al[mi][0] = *(const uint32_t*)p;
                al[mi][1] = *(const uint32_t*)(p + 8 * ROWB);
                al[mi][2] = *(const uint32_t*)(p + 16);
                al[mi][3] = *(const uint32_t*)(p + 8 * ROWB + 16);
            }
#pragma unroll
            for (int mi = 0; mi < 4; mi++)
#pragma unroll
                for (int ni = 0; ni < 4; ni++) mma16816(acc[mi][ni], al[mi], bh[ni]);
        }
        __syncthreads();
    }

    // epilogue
#pragma unroll
    for (int mi = 0; mi < 4; mi++) {
        int r0 = m0 + wm * 64 + mi * 16 + g;
#pragma unroll
        for (int ni = 0; ni < 4; ni++) {
            int c0 = n0 + wn * 32 + ni * 8 + ((lane & 3) << 1);
            float2 lo, hi2;
            lo.x = acc[mi][ni][0];
            lo.y = acc[mi][ni][1];
            hi2.x = acc[mi][ni][2];
            hi2.y = acc[mi][ni][3];
            if (act == 1) {
                lo.x = lo.x / (1.f + expf(-lo.x));
                lo.y = lo.y / (1.f + expf(-lo.y));
                hi2.x = hi2.x / (1.f + expf(-hi2.x));
                hi2.y = hi2.y / (1.f + expf(-hi2.y));
            }
            *(float2*)(C + (size_t)r0 * N + c0) = lo;
            *(float2*)(C + (size_t)(r0 + 8) * N + c0) = hi2;
        }
    }
}

// ------------- small projections: beta (12) and g (6) per token --------------
__global__ void __launch_bounds__(256) proj_small(const float* __restrict__ x,
                                                  const float* __restrict__ Wb,
                                                  const float* __restrict__ Wa,
                                                  const float* __restrict__ A_log,
                                                  const float* __restrict__ dt_bias) {
    int warp = (blockIdx.x * blockDim.x + threadIdx.x) >> 5;
    int l = threadIdx.x & 31;
    int t = warp / 18;
    int o = warp % 18;
    const float* xr = x + (size_t)t * DD;
    const float* wr = (o < 12) ? (Wb + (size_t)o * DD) : (Wa + (size_t)(o - 12) * DD);
    float s = 0.f;
    for (int i = l; i < DD; i += 32) s = fmaf(xr[i], wr[i], s);
#pragma unroll
    for (int off = 16; off > 0; off >>= 1) s += __shfl_xor_sync(0xffffffffu, s, off);
    if (l == 0) {
        if (o < 12) {
            d_betabuf[(size_t)t * 12 + o] = 2.f / (1.f + expf(-s));
        } else {
            int h = o - 12;
            float z = s + dt_bias[h];
            float sp = (z > 20.f) ? z : log1pf(expf(z));
            d_gbuf[(size_t)t * 6 + h] = -expf(A_log[h]) * sp;
        }
    }
}

// ------------- normalize k rows (length 256) in place ------------------------
__global__ void __launch_bounds__(256) knorm_kernel() {
    int warp = (blockIdx.x * blockDim.x + threadIdx.x) >> 5;
    int l = threadIdx.x & 31;
    float* row = d_kbuf + (size_t)warp * KK;
    float vr[8];
    float s = 0.f;
#pragma unroll
    for (int i = 0; i < 8; i++) {
        vr[i] = row[l + 32 * i];
        s = fmaf(vr[i], vr[i], s);
    }
#pragma unroll
    for (int off = 16; off > 0; off >>= 1) s += __shfl_xor_sync(0xffffffffu, s, off);
    float inv = 1.f / fmaxf(sqrtf(s), 1e-12f);
#pragma unroll
    for (int i = 0; i < 8; i++) row[l + 32 * i] = vr[i] * inv;
}

// ------------- recurrence: 96 persistent CTAs, state in registers ------------
__global__ void __launch_bounds__(256, 1) recurrence_kernel() {
    const int cta = blockIdx.x;
    const int bh = cta >> 2;
    const int vc = cta & 3;
    const int b = bh / HH;
    const int h = bh % HH;
    const int w = threadIdx.x >> 5;
    const int l = threadIdx.x & 31;
    const int vbase = vc * 128 + w * 16;

    float hst[8][16];
#pragma unroll
    for (int i = 0; i < 8; i++)
#pragma unroll
        for (int c = 0; c < 16; c++) hst[i][c] = 0.f;

    const float scale = 0.0625f;

    for (int t = 0; t < TT; t++) {
        const size_t tb = (size_t)b * TT + t;
        const float* qp = d_qbuf + tb * KEY_DIM + h * KK;
        const float* k0p = d_kbuf + tb * (KEY_DIM * NHH) + h * KK;
        const float* k1p = k0p + HH * KK;
        const float* v0p = d_vbuf + tb * (VAL_DIM * NHH) + h * VV + vbase;
        const float* v1p = v0p + HH * VV;
        float gt = d_gbuf[tb * HH + h];
        float b0 = d_betabuf[tb * 12 + h];
        float b1 = d_betabuf[tb * 12 + 6 + h];
        float eg = expf(gt);

        float qs[8], a0[8], a1[8];
#pragma unroll
        for (int i = 0; i < 8; i++) {
            int kk = l + 32 * i;
            qs[i] = qp[kk] * scale;
            a0[i] = k0p[kk];
            a1[i] = k1p[kk];
        }
        float vv0[16], vv1[16];
#pragma unroll
        for (int c = 0; c < 16; c++) {
            vv0[c] = v0p[c];
            vv1[c] = v1p[c];
        }

        float acc[16];
#pragma unroll
        for (int c = 0; c < 16; c++) acc[c] = 0.f;
#pragma unroll
        for (int i = 0; i < 8; i++)
#pragma unroll
            for (int c = 0; c < 16; c++) {
                hst[i][c] *= eg;
                acc[c] = fmaf(hst[i][c], a0[i], acc[c]);
            }
#pragma unroll
        for (int c = 0; c < 16; c++)
#pragma unroll
            for (int off = 16; off > 0; off >>= 1)
                acc[c] += __shfl_xor_sync(0xffffffffu, acc[c], off);
#pragma unroll
        for (int c = 0; c < 16; c++) vv0[c] -= acc[c];
#pragma unroll
        for (int i = 0; i < 8; i++) a0[i] *= b0;

#pragma unroll
        for (int c = 0; c < 16; c++) acc[c] = 0.f;
#pragma unroll
        for (int i = 0; i < 8; i++)
#pragma unroll
            for (int c = 0; c < 16; c++) {
                hst[i][c] = fmaf(a0[i], vv0[c], hst[i][c]);
                acc[c] = fmaf(hst[i][c], a1[i], acc[c]);
            }
#pragma unroll
        for (int c = 0; c < 16; c++)
#pragma unroll
            for (int off = 16; off > 0; off >>= 1)
                acc[c] += __shfl_xor_sync(0xffffffffu, acc[c], off);
#pragma unroll
        for (int c = 0; c < 16; c++) vv1[c] -= acc[c];
#pragma unroll
        for (int i = 0; i < 8; i++) a1[i] *= b1;

#pragma unroll
        for (int c = 0; c < 16; c++) acc[c] = 0.f;
#pragma unroll
        for (int i = 0; i < 8; i++)
#pragma unroll
            for (int c = 0; c < 16; c++) {
                hst[i][c] = fmaf(a1[i], vv1[c], hst[i][c]);
                acc[c] = fmaf(hst[i][c], qs[i], acc[c]);
            }
#pragma unroll
        for (int c = 0; c < 16; c++)
#pragma unroll
            for (int off = 16; off > 0; off >>= 1)
                acc[c] += __shfl_xor_sync(0xffffffffu, acc[c], off);

        float* op = d_omid + tb * VAL_DIM + h * VV + vbase;
#pragma unroll
        for (int c = 0; c < 16; c++)
            if (l == c) op[c] = acc[c];
    }
}

// ------------- gated RMSNorm over V=512 -> bf16 hi/lo ------------------------
__global__ void __launch_bounds__(256) rmsgate_kernel(const float* __restrict__ wnorm) {
    int warp = (blockIdx.x * blockDim.x + threadIdx.x) >> 5;  // row = (b,t,h)
    int l = threadIdx.x & 31;
    const float* row = d_omid + (size_t)warp * VV;
    const float* gr = d_gatebuf + (size_t)warp * VV;
    float vr[16];
    float s = 0.f;
#pragma unroll
    for (int i = 0; i < 16; i++) {
        vr[i] = row[l + 32 * i];
        s = fmaf(vr[i], vr[i], s);
    }
#pragma unroll
    for (int off = 16; off > 0; off >>= 1) s += __shfl_xor_sync(0xffffffffu, s, off);
    float rinv = rsqrtf(s * (1.f / (float)VV) + 1e-5f);
#pragma unroll
    for (int i = 0; i < 16; i++) {
        int idx = l + 32 * i;
        float gv = gr[idx];
        float sig = 1.f / (1.f + expf(-gv));
        float val = vr[i] * rinv * wnorm[idx] * sig;
        __nv_bfloat16 hh = __float2bfloat16(val);
        d_onhi[(size_t)warp * VV + idx] = hh;
        d_onlo[(size_t)warp * VV + idx] = __float2bfloat16(val - __bfloat162float(hh));
    }
}

// ---------------------------------------------------------------------------
extern "C" void kernel_launch(void* const* d_in, const int* in_sizes, int n_in,
                              void* d_out, int out_size) {
    const float* x = (const float*)d_in[0];
    const float* Wq = (const float*)d_in[1];
    const float* Wk = (const float*)d_in[2];
    const float* Wv = (const float*)d_in[3];
    const float* Wb = (const float*)d_in[4];
    const float* Wa = (const float*)d_in[5];
    const float* A_log = (const float*)d_in[6];
    const float* dt_bias = (const float*)d_in[7];
    const float* Wg = (const float*)d_in[8];
    const float* Wo = (const float*)d_in[9];
    const float* o_norm_w = (const float*)d_in[10];
    float* out = (float*)d_out;

    float* qbuf;    cudaGetSymbolAddress((void**)&qbuf, d_qbuf);
    float* kbuf;    cudaGetSymbolAddress((void**)&kbuf, d_kbuf);
    float* vbuf;    cudaGetSymbolAddress((void**)&vbuf, d_vbuf);
    float* gatebuf; cudaGetSymbolAddress((void**)&gatebuf, d_gatebuf);

    __nv_bfloat16 *xhi, *xlo, *wqhi, *wqlo, *wkhi, *wklo, *wvhi, *wvlo,
                  *wghi, *wglo, *wohi, *wolo, *onhi, *onlo;
    cudaGetSymbolAddress((void**)&xhi, d_xhi);   cudaGetSymbolAddress((void**)&xlo, d_xlo);
    cudaGetSymbolAddress((void**)&wqhi, d_wqhi); cudaGetSymbolAddress((void**)&wqlo, d_wqlo);
    cudaGetSymbolAddress((void**)&wkhi, d_wkhi); cudaGetSymbolAddress((void**)&wklo, d_wklo);
    cudaGetSymbolAddress((void**)&wvhi, d_wvhi); cudaGetSymbolAddress((void**)&wvlo, d_wvlo);
    cudaGetSymbolAddress((void**)&wghi, d_wghi); cudaGetSymbolAddress((void**)&wglo, d_wglo);
    cudaGetSymbolAddress((void**)&wohi, d_wohi); cudaGetSymbolAddress((void**)&wolo, d_wolo);
    cudaGetSymbolAddress((void**)&onhi, d_onhi); cudaGetSymbolAddress((void**)&onlo, d_onlo);

    cudaFuncSetAttribute(gemm_tc, cudaFuncAttributeMaxDynamicSharedMemorySize, GEMM_SMEM);

    // fp32 -> bf16 hi/lo splits
    auto split = [&](const float* src, __nv_bfloat16* hi, __nv_bfloat16* lo, int n) {
        int n4 = n / 4;
        split_bf16<<<(n4 + 255) / 256, 256>>>((const float4*)src,
                                              (__nv_bfloat162*)hi, (__nv_bfloat162*)lo, n4);
    };
    split(x, xhi, xlo, NTOK * DD);
    split(Wq, wqhi, wqlo, KEY_DIM * DD);
    split(Wk, wkhi, wklo, KEY_DIM * NHH * DD);
    split(Wv, wvhi, wvlo, VAL_DIM * NHH * DD);
    split(Wg, wghi, wglo, VAL_DIM * DD);
    split(Wo, wohi, wolo, DD * VAL_DIM);

    // projections (mma.sync bf16 3-term split, fused SiLU where needed)
    gemm_tc<<<dim3(KEY_DIM / GBN, NTOK / GBM), 256, GEMM_SMEM>>>(xhi, xlo, wqhi, wqlo, qbuf, DD, KEY_DIM, 1);
    gemm_tc<<<dim3(KEY_DIM * NHH / GBN, NTOK / GBM), 256, GEMM_SMEM>>>(xhi, xlo, wkhi, wklo, kbuf, DD, KEY_DIM * NHH, 1);
    gemm_tc<<<dim3(VAL_DIM * NHH / GBN, NTOK / GBM), 256, GEMM_SMEM>>>(xhi, xlo, wvhi, wvlo, vbuf, DD, VAL_DIM * NHH, 1);
    gemm_tc<<<dim3(VAL_DIM / GBN, NTOK / GBM), 256, GEMM_SMEM>>>(xhi, xlo, wghi, wglo, gatebuf, DD, VAL_DIM, 0);

    // beta / g
    proj_small<<<(NTOK * 18) / 8, 256>>>(x, Wb, Wa, A_log, dt_bias);

    // normalize k rows
    knorm_kernel<<<(NTOK * NHH * HH) / 8, 256>>>();

    // sequential recurrence
    recurrence_kernel<<<96, 256>>>();

    // gated RMSNorm -> bf16 hi/lo
    rmsgate_kernel<<<(NTOK * HH) / 8, 256>>>(o_norm_w);

    // output projection
    gemm_tc<<<dim3(DD / GBN, NTOK / GBM), 256, GEMM_SMEM>>>(onhi, onlo, wohi, wolo, out, VAL_DIM, DD, 0);
}

// round 7
// speedup vs baseline: 1.8489x; 1.2144x over previous
#include <cuda_runtime.h>
#include <cuda_bf16.h>
#include <math.h>
#include <stdint.h>

// Problem constants
#define BB 4
#define TT 512
#define DD 2048
#define HH 6
#define KK 256
#define VV 512
#define NHH 2
#define NTOK (BB * TT)          // 2048
#define KEY_DIM (HH * KK)       // 1536
#define VAL_DIM (HH * VV)       // 3072

// ---------------- scratch (static device globals; no allocation) -------------
__device__ float d_qbuf[NTOK * KEY_DIM];
__device__ float d_kbuf[NTOK * KEY_DIM * NHH];
__device__ float d_vbuf[NTOK * VAL_DIM * NHH];
__device__ float d_gatebuf[NTOK * VAL_DIM];
__device__ float d_betabuf[NTOK * NHH * HH];
__device__ float d_gbuf[NTOK * HH];
__device__ float d_omid[NTOK * VAL_DIM];

// bf16 split buffers (hi/lo)
__device__ __nv_bfloat16 d_xhi[NTOK * DD],  d_xlo[NTOK * DD];
__device__ __nv_bfloat16 d_wqhi[KEY_DIM * DD], d_wqlo[KEY_DIM * DD];
__device__ __nv_bfloat16 d_wkhi[KEY_DIM * NHH * DD], d_wklo[KEY_DIM * NHH * DD];
__device__ __nv_bfloat16 d_wvhi[VAL_DIM * NHH * DD], d_wvlo[VAL_DIM * NHH * DD];
__device__ __nv_bfloat16 d_wghi[VAL_DIM * DD], d_wglo[VAL_DIM * DD];
__device__ __nv_bfloat16 d_wohi[DD * VAL_DIM], d_wolo[DD * VAL_DIM];
__device__ __nv_bfloat16 d_onhi[NTOK * VAL_DIM], d_onlo[NTOK * VAL_DIM];

// =================== helpers =================================================
#define CP_ASYNC16(dst, src) \
    asm volatile("cp.async.cg.shared.global [%0], [%1], 16;" :: "r"(dst), "l"(src))
#define CP_COMMIT() asm volatile("cp.async.commit_group;" ::: "memory")

__device__ __forceinline__ uint32_t smem_u32(const void* p) {
    uint32_t a;
    asm("{ .reg .u64 t; cvta.to.shared.u64 t, %1; cvt.u32.u64 %0, t; }" : "=r"(a) : "l"(p));
    return a;
}

__device__ __forceinline__ void mma16816(float* c, const uint32_t* a, const uint32_t* b) {
    asm volatile(
        "mma.sync.aligned.m16n8k16.row.col.f32.bf16.bf16.f32 "
        "{%0,%1,%2,%3}, {%4,%5,%6,%7}, {%8,%9}, {%0,%1,%2,%3};"
        : "+f"(c[0]), "+f"(c[1]), "+f"(c[2]), "+f"(c[3])
        : "r"(a[0]), "r"(a[1]), "r"(a[2]), "r"(a[3]), "r"(b[0]), "r"(b[1]));
}

// =================== fp32 -> bf16 hi/lo split ================================
__global__ void __launch_bounds__(256) split_bf16(const float4* __restrict__ src,
                                                  __nv_bfloat162* __restrict__ hi,
                                                  __nv_bfloat162* __restrict__ lo,
                                                  int n4) {
    int i = blockIdx.x * blockDim.x + threadIdx.x;
    if (i >= n4) return;
    float4 a = src[i];
    __nv_bfloat16 h0 = __float2bfloat16(a.x);
    __nv_bfloat16 h1 = __float2bfloat16(a.y);
    __nv_bfloat16 h2 = __float2bfloat16(a.z);
    __nv_bfloat16 h3 = __float2bfloat16(a.w);
    hi[2 * i + 0] = __nv_bfloat162(h0, h1);
    hi[2 * i + 1] = __nv_bfloat162(h2, h3);
    lo[2 * i + 0] = __nv_bfloat162(__float2bfloat16(a.x - __bfloat162float(h0)),
                                   __float2bfloat16(a.y - __bfloat162float(h1)));
    lo[2 * i + 1] = __nv_bfloat162(__float2bfloat16(a.z - __bfloat162float(h2)),
                                   __float2bfloat16(a.w - __bfloat162float(h3)));
}

// =================== mma.sync bf16 GEMM body =================================
// Block tile 128(M) x 256(N), BK=32, 8 warps (2x4), warp tile 64x64.
// 3-stage cp.async pipeline. 3-term split: D += Ah*Bh + Al*Bh + Ah*Bl.
// Pointers are pre-offset to the block origin. ROWB = 80 bytes.
#define ST_A 10240
#define ST_B 20480
#define STAGE_B 61440
#define GEMM_SMEM (3 * STAGE_B)      // 184320

__device__ __forceinline__ void gemm_body(
    const __nv_bfloat16* __restrict__ Ahi, const __nv_bfloat16* __restrict__ Alo,
    const __nv_bfloat16* __restrict__ Bhi, const __nv_bfloat16* __restrict__ Blo,
    float* __restrict__ Cblk, int Kd, int ldC, int act, char* smem)
{
    const uint32_t sb = smem_u32(smem);
    const int tid = threadIdx.x;
    const int lane = tid & 31;
    const int wid = tid >> 5;
    const int wm = wid >> 2;          // 0..1
    const int wn = wid & 3;           // 0..3
    const int g = lane >> 2;          // 0..7
    const int q4b = (lane & 3) << 2;  // byte offset in k
    const int NS = Kd / 32;

    auto load_stage = [&](int s, int buf) {
        const uint32_t base = sb + (uint32_t)buf * STAGE_B;
        const int k0 = s * 32;
#pragma unroll
        for (int i = 0; i < 12; i++) {
            int c = tid + i * 256;    // 0..3071
            uint32_t dst;
            const __nv_bfloat16* src;
            if (c < 1024) {           // A hi/lo: 128 rows x 4 chunks
                int half = c >> 9, idx = c & 511, row = idx >> 2, kc = idx & 3;
                dst = base + (uint32_t)half * ST_A + (uint32_t)row * 80u + (uint32_t)kc * 16u;
                src = (half ? Alo : Ahi) + (size_t)row * Kd + k0 + kc * 8;
            } else {                  // B hi/lo: 256 rows x 4 chunks
                int cb = c - 1024, half = cb >> 10, idx = cb & 1023, row = idx >> 2, kc = idx & 3;
                dst = base + 2u * ST_A + (uint32_t)half * ST_B + (uint32_t)row * 80u + (uint32_t)kc * 16u;
                src = (half ? Blo : Bhi) + (size_t)row * Kd + k0 + kc * 8;
            }
            CP_ASYNC16(dst, (const char*)src);
        }
        CP_COMMIT();
    };

    float acc[4][8][4];
#pragma unroll
    for (int mi = 0; mi < 4; mi++)
#pragma unroll
        for (int ni = 0; ni < 8; ni++)
#pragma unroll
            for (int r = 0; r < 4; r++) acc[mi][ni][r] = 0.f;

    load_stage(0, 0);
    load_stage(1, 1);

    int buf = 0;
    for (int s = 0; s < NS; s++) {
        if (s + 1 < NS) {
            asm volatile("cp.async.wait_group 1;" ::: "memory");
        } else {
            asm volatile("cp.async.wait_group 0;" ::: "memory");
        }
        __syncthreads();

        const char* st = smem + buf * STAGE_B;
#pragma unroll
        for (int ks = 0; ks < 2; ks++) {
            const int kb = ks * 32 + q4b;
            uint32_t ah[4][4], al[4][4], bb[8][2];
            // A-hi frags
#pragma unroll
            for (int mi = 0; mi < 4; mi++) {
                const char* p = st + (wm * 64 + mi * 16 + g) * 80 + kb;
                ah[mi][0] = *(const uint32_t*)p;
                ah[mi][1] = *(const uint32_t*)(p + 8 * 80);
                ah[mi][2] = *(const uint32_t*)(p + 16);
                ah[mi][3] = *(const uint32_t*)(p + 8 * 80 + 16);
            }
            // B-hi frags
#pragma unroll
            for (int ni = 0; ni < 8; ni++) {
                const char* p = st + 2 * ST_A + (wn * 64 + ni * 8 + g) * 80 + kb;
                bb[ni][0] = *(const uint32_t*)p;
                bb[ni][1] = *(const uint32_t*)(p + 16);
            }
#pragma unroll
            for (int mi = 0; mi < 4; mi++)
#pragma unroll
                for (int ni = 0; ni < 8; ni++) mma16816(acc[mi][ni], ah[mi], bb[ni]);
            // A-lo frags, multiply with B-hi
#pragma unroll
            for (int mi = 0; mi < 4; mi++) {
                const char* p = st + ST_A + (wm * 64 + mi * 16 + g) * 80 + kb;
                al[mi][0] = *(const uint32_t*)p;
                al[mi][1] = *(const uint32_t*)(p + 8 * 80);
                al[mi][2] = *(const uint32_t*)(p + 16);
                al[mi][3] = *(const uint32_t*)(p + 8 * 80 + 16);
            }
#pragma unroll
            for (int mi = 0; mi < 4; mi++)
#pragma unroll
                for (int ni = 0; ni < 8; ni++) mma16816(acc[mi][ni], al[mi], bb[ni]);
            // B-lo frags (reuse bb), multiply with A-hi
#pragma unroll
            for (int ni = 0; ni < 8; ni++) {
                const char* p = st + 2 * ST_A + ST_B + (wn * 64 + ni * 8 + g) * 80 + kb;
                bb[ni][0] = *(const uint32_t*)p;
                bb[ni][1] = *(const uint32_t*)(p + 16);
            }
#pragma unroll
            for (int mi = 0; mi < 4; mi++)
#pragma unroll
                for (int ni = 0; ni < 8; ni++) mma16816(acc[mi][ni], ah[mi], bb[ni]);
        }
        if (s + 2 < NS) load_stage(s + 2, (s + 2) % 3);
        buf = (buf + 1) % 3;
    }

    // epilogue
#pragma unroll
    for (int mi = 0; mi < 4; mi++) {
        int r0 = wm * 64 + mi * 16 + g;
#pragma unroll
        for (int ni = 0; ni < 8; ni++) {
            int c0 = wn * 64 + ni * 8 + ((lane & 3) << 1);
            float2 lo, hi2;
            lo.x = acc[mi][ni][0];
            lo.y = acc[mi][ni][1];
            hi2.x = acc[mi][ni][2];
            hi2.y = acc[mi][ni][3];
            if (act == 1) {
                lo.x = lo.x / (1.f + expf(-lo.x));
                lo.y = lo.y / (1.f + expf(-lo.y));
                hi2.x = hi2.x / (1.f + expf(-hi2.x));
                hi2.y = hi2.y / (1.f + expf(-hi2.y));
            }
            *(float2*)(Cblk + (size_t)r0 * ldC + c0) = lo;
            *(float2*)(Cblk + (size_t)(r0 + 8) * ldC + c0) = hi2;
        }
    }
}

// fused q/k/v/gate projection: grid (54, 16)
__global__ void __launch_bounds__(256, 1) qkvg_gemm() {
    extern __shared__ __align__(128) char smem[];
    const int nb = blockIdx.x;
    const int mb = blockIdx.y;
    const __nv_bfloat16 *Bhi, *Blo;
    float* C;
    int ldC, act;
    if (nb < 6) {
        Bhi = d_wqhi + (size_t)nb * 256 * DD;  Blo = d_wqlo + (size_t)nb * 256 * DD;
        C = d_qbuf + nb * 256;  ldC = KEY_DIM;  act = 1;
    } else if (nb < 18) {
        int t = nb - 6;
        Bhi = d_wkhi + (size_t)t * 256 * DD;   Blo = d_wklo + (size_t)t * 256 * DD;
        C = d_kbuf + t * 256;   ldC = KEY_DIM * NHH;  act = 1;
    } else if (nb < 42) {
        int t = nb - 18;
        Bhi = d_wvhi + (size_t)t * 256 * DD;   Blo = d_wvlo + (size_t)t * 256 * DD;
        C = d_vbuf + t * 256;   ldC = VAL_DIM * NHH;  act = 1;
    } else {
        int t = nb - 42;
        Bhi = d_wghi + (size_t)t * 256 * DD;   Blo = d_wglo + (size_t)t * 256 * DD;
        C = d_gatebuf + t * 256;  ldC = VAL_DIM;  act = 0;
    }
    gemm_body(d_xhi + (size_t)mb * 128 * DD, d_xlo + (size_t)mb * 128 * DD,
              Bhi, Blo, C + (size_t)mb * 128 * ldC, DD, ldC, act, smem);
}

// generic GEMM (used for output projection): grid (N/256, M/128)
__global__ void __launch_bounds__(256, 1) gemm_out(
    const __nv_bfloat16* __restrict__ Ahi, const __nv_bfloat16* __restrict__ Alo,
    const __nv_bfloat16* __restrict__ Bhi, const __nv_bfloat16* __restrict__ Blo,
    float* __restrict__ C, int Kd, int N) {
    extern __shared__ __align__(128) char smem[];
    gemm_body(Ahi + (size_t)blockIdx.y * 128 * Kd, Alo + (size_t)blockIdx.y * 128 * Kd,
              Bhi + (size_t)blockIdx.x * 256 * Kd, Blo + (size_t)blockIdx.x * 256 * Kd,
              C + (size_t)blockIdx.y * 128 * N + blockIdx.x * 256, Kd, N, 0, smem);
}

// ------------- small projections: beta (12) and g (6) per token --------------
__global__ void __launch_bounds__(256) proj_small(const float* __restrict__ x,
                                                  const float* __restrict__ Wb,
                                                  const float* __restrict__ Wa,
                                                  const float* __restrict__ A_log,
                                                  const float* __restrict__ dt_bias) {
    int warp = (blockIdx.x * blockDim.x + threadIdx.x) >> 5;
    int l = threadIdx.x & 31;
    int t = warp / 18;
    int o = warp % 18;
    const float* xr = x + (size_t)t * DD;
    const float* wr = (o < 12) ? (Wb + (size_t)o * DD) : (Wa + (size_t)(o - 12) * DD);
    float s = 0.f;
    for (int i = l; i < DD; i += 32) s = fmaf(xr[i], wr[i], s);
#pragma unroll
    for (int off = 16; off > 0; off >>= 1) s += __shfl_xor_sync(0xffffffffu, s, off);
    if (l == 0) {
        if (o < 12) {
            d_betabuf[(size_t)t * 12 + o] = 2.f / (1.f + expf(-s));
        } else {
            int h = o - 12;
            float z = s + dt_bias[h];
            float sp = (z > 20.f) ? z : log1pf(expf(z));
            d_gbuf[(size_t)t * 6 + h] = -expf(A_log[h]) * sp;
        }
    }
}

// ------------- normalize k rows (length 256) in place ------------------------
__global__ void __launch_bounds__(256) knorm_kernel() {
    int warp = (blockIdx.x * blockDim.x + threadIdx.x) >> 5;
    int l = threadIdx.x & 31;
    float* row = d_kbuf + (size_t)warp * KK;
    float vr[8];
    float s = 0.f;
#pragma unroll
    for (int i = 0; i < 8; i++) {
        vr[i] = row[l + 32 * i];
        s = fmaf(vr[i], vr[i], s);
    }
#pragma unroll
    for (int off = 16; off > 0; off >>= 1) s += __shfl_xor_sync(0xffffffffu, s, off);
    float inv = 1.f / fmaxf(sqrtf(s), 1e-12f);
#pragma unroll
    for (int i = 0; i < 8; i++) row[l + 32 * i] = vr[i] * inv;
}

// ------------- recurrence: 96 persistent CTAs, state in registers ------------
// CTA = (bh, vchunk of 128 cols). Warp w: 16 cols. Lane l: k-slice j = l&7
// (32 consecutive k), v sub-block s4 = (l>>3)*4 (4 cols). Reduction over k =
// in-thread 32 + 3 shuffles across the 8-lane k-group.
// Decay folded into scalar carry S (h_true = S * hs), renormalized when small.
__global__ void __launch_bounds__(256, 1) recurrence_kernel() {
    const int cta = blockIdx.x;
    const int bh = cta >> 2;
    const int vc = cta & 3;
    const int b = bh / HH;
    const int h = bh % HH;
    const int w = threadIdx.x >> 5;
    const int l = threadIdx.x & 31;
    const int j = l & 7;
    const int s4 = (l >> 3) << 2;
    const int vbase = vc * 128 + w * 16;

    float hs[32][4];
#pragma unroll
    for (int i = 0; i < 32; i++)
#pragma unroll
        for (int c = 0; c < 4; c++) hs[i][c] = 0.f;

    float S = 1.f;

    for (int t = 0; t < TT; t++) {
        const size_t tb = (size_t)b * TT + t;
        const float* qp  = d_qbuf + tb * KEY_DIM + h * KK + j * 32;
        const float* k0p = d_kbuf + tb * (KEY_DIM * NHH) + h * KK + j * 32;
        const float* k1p = k0p + HH * KK;
        const float* v0p = d_vbuf + tb * (VAL_DIM * NHH) + h * VV + vbase;
        const float* v1p = v0p + HH * VV;
        const float eg = expf(d_gbuf[tb * HH + h]);
        const float b0 = d_betabuf[tb * 12 + h];
        const float b1 = d_betabuf[tb * 12 + 6 + h];

        S *= eg;
        if (S < 1e-12f) {     // uniform across CTA (same chain)
#pragma unroll
            for (int i = 0; i < 32; i++)
#pragma unroll
                for (int c = 0; c < 4; c++) hs[i][c] *= S;
            S = 1.f;
        }

        // ---- householder 0 ----
        float a0[32];
#pragma unroll
        for (int m = 0; m < 8; m++) {
            float4 t4 = *(const float4*)(k0p + 4 * m);
            a0[4 * m + 0] = t4.x; a0[4 * m + 1] = t4.y;
            a0[4 * m + 2] = t4.z; a0[4 * m + 3] = t4.w;
        }
        float4 vv0 = *(const float4*)(v0p + s4);
        float p[4] = {0.f, 0.f, 0.f, 0.f};
#pragma unroll
        for (int i = 0; i < 32; i++)
#pragma unroll
            for (int c = 0; c < 4; c++) p[c] = fmaf(hs[i][c], a0[i], p[c]);
#pragma unroll
        for (int c = 0; c < 4; c++) {
            p[c] += __shfl_xor_sync(0xffffffffu, p[c], 1);
            p[c] += __shfl_xor_sync(0xffffffffu, p[c], 2);
            p[c] += __shfl_xor_sync(0xffffffffu, p[c], 4);
        }
        const float i0 = b0 / S;
        float w0[4];
        w0[0] = (vv0.x - S * p[0]) * i0;
        w0[1] = (vv0.y - S * p[1]) * i0;
        w0[2] = (vv0.z - S * p[2]) * i0;
        w0[3] = (vv0.w - S * p[3]) * i0;
#pragma unroll
        for (int i = 0; i < 32; i++)
#pragma unroll
            for (int c = 0; c < 4; c++) hs[i][c] = fmaf(a0[i], w0[c], hs[i][c]);

        // ---- householder 1 ----
        float a1[32];
#pragma unroll
        for (int m = 0; m < 8; m++) {
            float4 t4 = *(const float4*)(k1p + 4 * m);
            a1[4 * m + 0] = t4.x; a1[4 * m + 1] = t4.y;
            a1[4 * m + 2] = t4.z; a1[4 * m + 3] = t4.w;
        }
        float4 vv1 = *(const float4*)(v1p + s4);
#pragma unroll
        for (int c = 0; c < 4; c++) p[c] = 0.f;
#pragma unroll
        for (int i = 0; i < 32; i++)
#pragma unroll
            for (int c = 0; c < 4; c++) p[c] = fmaf(hs[i][c], a1[i], p[c]);
#pragma unroll
        for (int c = 0; c < 4; c++) {
            p[c] += __shfl_xor_sync(0xffffffffu, p[c], 1);
            p[c] += __shfl_xor_sync(0xffffffffu, p[c], 2);
            p[c] += __shfl_xor_sync(0xffffffffu, p[c], 4);
        }
        const float i1 = b1 / S;
        float w1[4];
        w1[0] = (vv1.x - S * p[0]) * i1;
        w1[1] = (vv1.y - S * p[1]) * i1;
        w1[2] = (vv1.z - S * p[2]) * i1;
        w1[3] = (vv1.w - S * p[3]) * i1;
#pragma unroll
        for (int i = 0; i < 32; i++)
#pragma unroll
            for (int c = 0; c < 4; c++) hs[i][c] = fmaf(a1[i], w1[c], hs[i][c]);

        // ---- output ----
        float qs[32];
#pragma unroll
        for (int m = 0; m < 8; m++) {
            float4 t4 = *(const float4*)(qp + 4 * m);
            qs[4 * m + 0] = t4.x; qs[4 * m + 1] = t4.y;
            qs[4 * m + 2] = t4.z; qs[4 * m + 3] = t4.w;
        }
#pragma unroll
        for (int c = 0; c < 4; c++) p[c] = 0.f;
#pragma unroll
        for (int i = 0; i < 32; i++)
#pragma unroll
            for (int c = 0; c < 4; c++) p[c] = fmaf(hs[i][c], qs[i], p[c]);
#pragma unroll
        for (int c = 0; c < 4; c++) {
            p[c] += __shfl_xor_sync(0xffffffffu, p[c], 1);
            p[c] += __shfl_xor_sync(0xffffffffu, p[c], 2);
            p[c] += __shfl_xor_sync(0xffffffffu, p[c], 4);
        }
        if (j == 0) {
            const float fs = S * 0.0625f;   // 256^-0.5
            float4 o4;
            o4.x = p[0] * fs; o4.y = p[1] * fs; o4.z = p[2] * fs; o4.w = p[3] * fs;
            *(float4*)(d_omid + tb * VAL_DIM + h * VV + vbase + s4) = o4;
        }
    }
}

// ------------- gated RMSNorm over V=512 -> bf16 hi/lo ------------------------
__global__ void __launch_bounds__(256) rmsgate_kernel(const float* __restrict__ wnorm) {
    int warp = (blockIdx.x * blockDim.x + threadIdx.x) >> 5;  // row = (b,t,h)
    int l = threadIdx.x & 31;
    const float* row = d_omid + (size_t)warp * VV;
    const float* gr = d_gatebuf + (size_t)warp * VV;
    float vr[16];
    float s = 0.f;
#pragma unroll
    for (int i = 0; i < 16; i++) {
        vr[i] = row[l + 32 * i];
        s = fmaf(vr[i], vr[i], s);
    }
#pragma unroll
    for (int off = 16; off > 0; off >>= 1) s += __shfl_xor_sync(0xffffffffu, s, off);
    float rinv = rsqrtf(s * (1.f / (float)VV) + 1e-5f);
#pragma unroll
    for (int i = 0; i < 16; i++) {
        int idx = l + 32 * i;
        float gv = gr[idx];
        float sig = 1.f / (1.f + expf(-gv));
        float val = vr[i] * rinv * wnorm[idx] * sig;
        __nv_bfloat16 hh = __float2bfloat16(val);
        d_onhi[(size_t)warp * VV + idx] = hh;
        d_onlo[(size_t)warp * VV + idx] = __float2bfloat16(val - __bfloat162float(hh));
    }
}

// ---------------------------------------------------------------------------
extern "C" void kernel_launch(void* const* d_in, const int* in_sizes, int n_in,
                              void* d_out, int out_size) {
    const float* x = (const float*)d_in[0];
    const float* Wq = (const float*)d_in[1];
    const float* Wk = (const float*)d_in[2];
    const float* Wv = (const float*)d_in[3];
    const float* Wb = (const float*)d_in[4];
    const float* Wa = (const float*)d_in[5];
    const float* A_log = (const float*)d_in[6];
    const float* dt_bias = (const float*)d_in[7];
    const float* Wg = (const float*)d_in[8];
    const float* Wo = (const float*)d_in[9];
    const float* o_norm_w = (const float*)d_in[10];
    float* out = (float*)d_out;

    __nv_bfloat16 *xhi, *xlo, *wqhi, *wqlo, *wkhi, *wklo, *wvhi, *wvlo,
                  *wghi, *wglo, *wohi, *wolo, *onhi, *onlo;
    cudaGetSymbolAddress((void**)&xhi, d_xhi);   cudaGetSymbolAddress((void**)&xlo, d_xlo);
    cudaGetSymbolAddress((void**)&wqhi, d_wqhi); cudaGetSymbolAddress((void**)&wqlo, d_wqlo);
    cudaGetSymbolAddress((void**)&wkhi, d_wkhi); cudaGetSymbolAddress((void**)&wklo, d_wklo);
    cudaGetSymbolAddress((void**)&wvhi, d_wvhi); cudaGetSymbolAddress((void**)&wvlo, d_wvlo);
    cudaGetSymbolAddress((void**)&wghi, d_wghi); cudaGetSymbolAddress((void**)&wglo, d_wglo);
    cudaGetSymbolAddress((void**)&wohi, d_wohi); cudaGetSymbolAddress((void**)&wolo, d_wolo);
    cudaGetSymbolAddress((void**)&onhi, d_onhi); cudaGetSymbolAddress((void**)&onlo, d_onlo);

    cudaFuncSetAttribute(qkvg_gemm, cudaFuncAttributeMaxDynamicSharedMemorySize, GEMM_SMEM);
    cudaFuncSetAttribute(gemm_out, cudaFuncAttributeMaxDynamicSharedMemorySize, GEMM_SMEM);

    // fp32 -> bf16 hi/lo splits
    auto split = [&](const float* src, __nv_bfloat16* hi, __nv_bfloat16* lo, int n) {
        int n4 = n / 4;
        split_bf16<<<(n4 + 255) / 256, 256>>>((const float4*)src,
                                              (__nv_bfloat162*)hi, (__nv_bfloat162*)lo, n4);
    };
    split(x, xhi, xlo, NTOK * DD);
    split(Wq, wqhi, wqlo, KEY_DIM * DD);
    split(Wk, wkhi, wklo, KEY_DIM * NHH * DD);
    split(Wv, wvhi, wvlo, VAL_DIM * NHH * DD);
    split(Wg, wghi, wglo, VAL_DIM * DD);
    split(Wo, wohi, wolo, DD * VAL_DIM);

    // beta / g (independent of GEMMs)
    proj_small<<<(NTOK * 18) / 8, 256>>>(x, Wb, Wa, A_log, dt_bias);

    // fused q/k/v/gate projections
    qkvg_gemm<<<dim3(54, 16), 256, GEMM_SMEM>>>();

    // normalize k rows
    knorm_kernel<<<(NTOK * NHH * HH) / 8, 256>>>();

    // sequential recurrence
    recurrence_kernel<<<96, 256>>>();

    // gated RMSNorm -> bf16 hi/lo
    rmsgate_kernel<<<(NTOK * HH) / 8, 256>>>(o_norm_w);

    // output projection
    gemm_out<<<dim3(DD / 256, NTOK / 128), 256, GEMM_SMEM>>>(onhi, onlo, wohi, wolo, out, VAL_DIM, DD);
}

// round 8
// speedup vs baseline: 1.9080x; 1.0320x over previous
#include <cuda_runtime.h>
#include <cuda_bf16.h>
#include <math.h>
#include <stdint.h>

// Problem constants
#define BB 4
#define TT 512
#define DD 2048
#define HH 6
#define KK 256
#define VV 512
#define NHH 2
#define NTOK (BB * TT)          // 2048
#define KEY_DIM (HH * KK)       // 1536
#define VAL_DIM (HH * VV)       // 3072

// ---------------- scratch (static device globals; no allocation) -------------
__device__ float d_qbuf[NTOK * KEY_DIM];
__device__ float d_kbuf[NTOK * KEY_DIM * NHH];
__device__ float d_vbuf[NTOK * VAL_DIM * NHH];
__device__ float d_gatebuf[NTOK * VAL_DIM];
__device__ float d_betabuf[NTOK * NHH * HH];
__device__ float d_gbuf[NTOK * HH];
__device__ float d_omid[NTOK * VAL_DIM];

// bf16 split buffers (hi/lo)
__device__ __nv_bfloat16 d_xhi[NTOK * DD],  d_xlo[NTOK * DD];
__device__ __nv_bfloat16 d_wqhi[KEY_DIM * DD], d_wqlo[KEY_DIM * DD];
__device__ __nv_bfloat16 d_wkhi[KEY_DIM * NHH * DD], d_wklo[KEY_DIM * NHH * DD];
__device__ __nv_bfloat16 d_wvhi[VAL_DIM * NHH * DD], d_wvlo[VAL_DIM * NHH * DD];
__device__ __nv_bfloat16 d_wghi[VAL_DIM * DD], d_wglo[VAL_DIM * DD];
__device__ __nv_bfloat16 d_wohi[DD * VAL_DIM], d_wolo[DD * VAL_DIM];
__device__ __nv_bfloat16 d_onhi[NTOK * VAL_DIM], d_onlo[NTOK * VAL_DIM];

// =================== helpers =================================================
#define CP_ASYNC16(dst, src) \
    asm volatile("cp.async.cg.shared.global [%0], [%1], 16;" :: "r"(dst), "l"(src))
#define CP_COMMIT() asm volatile("cp.async.commit_group;" ::: "memory")

__device__ __forceinline__ uint32_t smem_u32(const void* p) {
    uint32_t a;
    asm("{ .reg .u64 t; cvta.to.shared.u64 t, %1; cvt.u32.u64 %0, t; }" : "=r"(a) : "l"(p));
    return a;
}

__device__ __forceinline__ void mma16816(float* c, const uint32_t* a, const uint32_t* b) {
    asm volatile(
        "mma.sync.aligned.m16n8k16.row.col.f32.bf16.bf16.f32 "
        "{%0,%1,%2,%3}, {%4,%5,%6,%7}, {%8,%9}, {%0,%1,%2,%3};"
        : "+f"(c[0]), "+f"(c[1]), "+f"(c[2]), "+f"(c[3])
        : "r"(a[0]), "r"(a[1]), "r"(a[2]), "r"(a[3]), "r"(b[0]), "r"(b[1]));
}

// =================== fp32 -> bf16 hi/lo split ================================
__global__ void __launch_bounds__(256) split_bf16(const float4* __restrict__ src,
                                                  __nv_bfloat162* __restrict__ hi,
                                                  __nv_bfloat162* __restrict__ lo,
                                                  int n4) {
    int i = blockIdx.x * blockDim.x + threadIdx.x;
    if (i >= n4) return;
    float4 a = src[i];
    __nv_bfloat16 h0 = __float2bfloat16(a.x);
    __nv_bfloat16 h1 = __float2bfloat16(a.y);
    __nv_bfloat16 h2 = __float2bfloat16(a.z);
    __nv_bfloat16 h3 = __float2bfloat16(a.w);
    hi[2 * i + 0] = __nv_bfloat162(h0, h1);
    hi[2 * i + 1] = __nv_bfloat162(h2, h3);
    lo[2 * i + 0] = __nv_bfloat162(__float2bfloat16(a.x - __bfloat162float(h0)),
                                   __float2bfloat16(a.y - __bfloat162float(h1)));
    lo[2 * i + 1] = __nv_bfloat162(__float2bfloat16(a.z - __bfloat162float(h2)),
                                   __float2bfloat16(a.w - __bfloat162float(h3)));
}

// =================== mma.sync bf16 GEMM body =================================
// Block tile 128(M) x 256(N), BK=32, 8 warps (2x4), warp tile 64x64.
// 3-stage cp.async pipeline. 3-term split: D += Ah*Bh + Al*Bh + Ah*Bl.
// Pointers are pre-offset to the block origin. ROWB = 80 bytes.
#define ST_A 10240
#define ST_B 20480
#define STAGE_B 61440
#define GEMM_SMEM (3 * STAGE_B)      // 184320

__device__ __forceinline__ void gemm_body(
    const __nv_bfloat16* __restrict__ Ahi, const __nv_bfloat16* __restrict__ Alo,
    const __nv_bfloat16* __restrict__ Bhi, const __nv_bfloat16* __restrict__ Blo,
    float* __restrict__ Cblk, int Kd, int ldC, int act, char* smem)
{
    const uint32_t sb = smem_u32(smem);
    const int tid = threadIdx.x;
    const int lane = tid & 31;
    const int wid = tid >> 5;
    const int wm = wid >> 2;          // 0..1
    const int wn = wid & 3;           // 0..3
    const int g = lane >> 2;          // 0..7
    const int q4b = (lane & 3) << 2;  // byte offset in k
    const int NS = Kd / 32;

    auto load_stage = [&](int s, int buf) {
        const uint32_t base = sb + (uint32_t)buf * STAGE_B;
        const int k0 = s * 32;
#pragma unroll
        for (int i = 0; i < 12; i++) {
            int c = tid + i * 256;    // 0..3071
            uint32_t dst;
            const __nv_bfloat16* src;
            if (c < 1024) {           // A hi/lo: 128 rows x 4 chunks
                int half = c >> 9, idx = c & 511, row = idx >> 2, kc = idx & 3;
                dst = base + (uint32_t)half * ST_A + (uint32_t)row * 80u + (uint32_t)kc * 16u;
                src = (half ? Alo : Ahi) + (size_t)row * Kd + k0 + kc * 8;
            } else {                  // B hi/lo: 256 rows x 4 chunks
                int cb = c - 1024, half = cb >> 10, idx = cb & 1023, row = idx >> 2, kc = idx & 3;
                dst = base + 2u * ST_A + (uint32_t)half * ST_B + (uint32_t)row * 80u + (uint32_t)kc * 16u;
                src = (half ? Blo : Bhi) + (size_t)row * Kd + k0 + kc * 8;
            }
            CP_ASYNC16(dst, (const char*)src);
        }
        CP_COMMIT();
    };

    float acc[4][8][4];
#pragma unroll
    for (int mi = 0; mi < 4; mi++)
#pragma unroll
        for (int ni = 0; ni < 8; ni++)
#pragma unroll
            for (int r = 0; r < 4; r++) acc[mi][ni][r] = 0.f;

    load_stage(0, 0);
    load_stage(1, 1);

    int buf = 0;
    for (int s = 0; s < NS; s++) {
        if (s + 1 < NS) {
            asm volatile("cp.async.wait_group 1;" ::: "memory");
        } else {
            asm volatile("cp.async.wait_group 0;" ::: "memory");
        }
        __syncthreads();

        const char* st = smem + buf * STAGE_B;
#pragma unroll
        for (int ks = 0; ks < 2; ks++) {
            const int kb = ks * 32 + q4b;
            uint32_t ah[4][4], al[4][4], bb[8][2];
            // A-hi frags
#pragma unroll
            for (int mi = 0; mi < 4; mi++) {
                const char* p = st + (wm * 64 + mi * 16 + g) * 80 + kb;
                ah[mi][0] = *(const uint32_t*)p;
                ah[mi][1] = *(const uint32_t*)(p + 8 * 80);
                ah[mi][2] = *(const uint32_t*)(p + 16);
                ah[mi][3] = *(const uint32_t*)(p + 8 * 80 + 16);
            }
            // B-hi frags
#pragma unroll
            for (int ni = 0; ni < 8; ni++) {
                const char* p = st + 2 * ST_A + (wn * 64 + ni * 8 + g) * 80 + kb;
                bb[ni][0] = *(const uint32_t*)p;
                bb[ni][1] = *(const uint32_t*)(p + 16);
            }
#pragma unroll
            for (int mi = 0; mi < 4; mi++)
#pragma unroll
                for (int ni = 0; ni < 8; ni++) mma16816(acc[mi][ni], ah[mi], bb[ni]);
            // A-lo frags, multiply with B-hi
#pragma unroll
            for (int mi = 0; mi < 4; mi++) {
                const char* p = st + ST_A + (wm * 64 + mi * 16 + g) * 80 + kb;
                al[mi][0] = *(const uint32_t*)p;
                al[mi][1] = *(const uint32_t*)(p + 8 * 80);
                al[mi][2] = *(const uint32_t*)(p + 16);
                al[mi][3] = *(const uint32_t*)(p + 8 * 80 + 16);
            }
#pragma unroll
            for (int mi = 0; mi < 4; mi++)
#pragma unroll
                for (int ni = 0; ni < 8; ni++) mma16816(acc[mi][ni], al[mi], bb[ni]);
            // B-lo frags (reuse bb), multiply with A-hi
#pragma unroll
            for (int ni = 0; ni < 8; ni++) {
                const char* p = st + 2 * ST_A + ST_B + (wn * 64 + ni * 8 + g) * 80 + kb;
                bb[ni][0] = *(const uint32_t*)p;
                bb[ni][1] = *(const uint32_t*)(p + 16);
            }
#pragma unroll
            for (int mi = 0; mi < 4; mi++)
#pragma unroll
                for (int ni = 0; ni < 8; ni++) mma16816(acc[mi][ni], ah[mi], bb[ni]);
        }
        if (s + 2 < NS) load_stage(s + 2, (s + 2) % 3);
        buf = (buf + 1) % 3;
    }

    // epilogue
#pragma unroll
    for (int mi = 0; mi < 4; mi++) {
        int r0 = wm * 64 + mi * 16 + g;
#pragma unroll
        for (int ni = 0; ni < 8; ni++) {
            int c0 = wn * 64 + ni * 8 + ((lane & 3) << 1);
            float2 lo, hi2;
            lo.x = acc[mi][ni][0];
            lo.y = acc[mi][ni][1];
            hi2.x = acc[mi][ni][2];
            hi2.y = acc[mi][ni][3];
            if (act == 1) {
                lo.x = lo.x / (1.f + expf(-lo.x));
                lo.y = lo.y / (1.f + expf(-lo.y));
                hi2.x = hi2.x / (1.f + expf(-hi2.x));
                hi2.y = hi2.y / (1.f + expf(-hi2.y));
            }
            *(float2*)(Cblk + (size_t)r0 * ldC + c0) = lo;
            *(float2*)(Cblk + (size_t)(r0 + 8) * ldC + c0) = hi2;
        }
    }
}

// fused q/k/v/gate projection: grid (54, 16)
__global__ void __launch_bounds__(256, 1) qkvg_gemm() {
    extern __shared__ __align__(128) char smem[];
    const int nb = blockIdx.x;
    const int mb = blockIdx.y;
    const __nv_bfloat16 *Bhi, *Blo;
    float* C;
    int ldC, act;
    if (nb < 6) {
        Bhi = d_wqhi + (size_t)nb * 256 * DD;  Blo = d_wqlo + (size_t)nb * 256 * DD;
        C = d_qbuf + nb * 256;  ldC = KEY_DIM;  act = 1;
    } else if (nb < 18) {
        int t = nb - 6;
        Bhi = d_wkhi + (size_t)t * 256 * DD;   Blo = d_wklo + (size_t)t * 256 * DD;
        C = d_kbuf + t * 256;   ldC = KEY_DIM * NHH;  act = 1;
    } else if (nb < 42) {
        int t = nb - 18;
        Bhi = d_wvhi + (size_t)t * 256 * DD;   Blo = d_wvlo + (size_t)t * 256 * DD;
        C = d_vbuf + t * 256;   ldC = VAL_DIM * NHH;  act = 1;
    } else {
        int t = nb - 42;
        Bhi = d_wghi + (size_t)t * 256 * DD;   Blo = d_wglo + (size_t)t * 256 * DD;
        C = d_gatebuf + t * 256;  ldC = VAL_DIM;  act = 0;
    }
    gemm_body(d_xhi + (size_t)mb * 128 * DD, d_xlo + (size_t)mb * 128 * DD,
              Bhi, Blo, C + (size_t)mb * 128 * ldC, DD, ldC, act, smem);
}

// generic GEMM (used for output projection): grid (N/256, M/128)
__global__ void __launch_bounds__(256, 1) gemm_out(
    const __nv_bfloat16* __restrict__ Ahi, const __nv_bfloat16* __restrict__ Alo,
    const __nv_bfloat16* __restrict__ Bhi, const __nv_bfloat16* __restrict__ Blo,
    float* __restrict__ C, int Kd, int N) {
    extern __shared__ __align__(128) char smem[];
    gemm_body(Ahi + (size_t)blockIdx.y * 128 * Kd, Alo + (size_t)blockIdx.y * 128 * Kd,
              Bhi + (size_t)blockIdx.x * 256 * Kd, Blo + (size_t)blockIdx.x * 256 * Kd,
              C + (size_t)blockIdx.y * 128 * N + blockIdx.x * 256, Kd, N, 0, smem);
}

// ------------- small projections: beta (12) and g (6) per token --------------
__global__ void __launch_bounds__(256) proj_small(const float* __restrict__ x,
                                                  const float* __restrict__ Wb,
                                                  const float* __restrict__ Wa,
                                                  const float* __restrict__ A_log,
                                                  const float* __restrict__ dt_bias) {
    int warp = (blockIdx.x * blockDim.x + threadIdx.x) >> 5;
    int l = threadIdx.x & 31;
    int t = warp / 18;
    int o = warp % 18;
    const float* xr = x + (size_t)t * DD;
    const float* wr = (o < 12) ? (Wb + (size_t)o * DD) : (Wa + (size_t)(o - 12) * DD);
    float s = 0.f;
    for (int i = l; i < DD; i += 32) s = fmaf(xr[i], wr[i], s);
#pragma unroll
    for (int off = 16; off > 0; off >>= 1) s += __shfl_xor_sync(0xffffffffu, s, off);
    if (l == 0) {
        if (o < 12) {
            d_betabuf[(size_t)t * 12 + o] = 2.f / (1.f + expf(-s));
        } else {
            int h = o - 12;
            float z = s + dt_bias[h];
            float sp = (z > 20.f) ? z : log1pf(expf(z));
            d_gbuf[(size_t)t * 6 + h] = -expf(A_log[h]) * sp;
        }
    }
}

// ------------- normalize k rows (length 256) in place ------------------------
__global__ void __launch_bounds__(256) knorm_kernel() {
    int warp = (blockIdx.x * blockDim.x + threadIdx.x) >> 5;
    int l = threadIdx.x & 31;
    float* row = d_kbuf + (size_t)warp * KK;
    float vr[8];
    float s = 0.f;
#pragma unroll
    for (int i = 0; i < 8; i++) {
        vr[i] = row[l + 32 * i];
        s = fmaf(vr[i], vr[i], s);
    }
#pragma unroll
    for (int off = 16; off > 0; off >>= 1) s += __shfl_xor_sync(0xffffffffu, s, off);
    float inv = 1.f / fmaxf(sqrtf(s), 1e-12f);
#pragma unroll
    for (int i = 0; i < 8; i++) row[l + 32 * i] = vr[i] * inv;
}

// ------------- recurrence: 96 persistent CTAs, state in registers ------------
// CTA = (bh, vchunk of 128 cols). Warp w: 16 cols. Lane l: k-slice j = l&7
// (32 consecutive k), v sub-block s4 = (l>>3)*4 (4 cols). Reduction over k =
// in-thread 32 + 3 shuffles across the 8-lane k-group.
// Decay folded into scalar carry S (h_true = S * hs), renormalized when small.
__global__ void __launch_bounds__(256, 1) recurrence_kernel() {
    const int cta = blockIdx.x;
    const int bh = cta >> 2;
    const int vc = cta & 3;
    const int b = bh / HH;
    const int h = bh % HH;
    const int w = threadIdx.x >> 5;
    const int l = threadIdx.x & 31;
    const int j = l & 7;
    const int s4 = (l >> 3) << 2;
    const int vbase = vc * 128 + w * 16;

    float hs[32][4];
#pragma unroll
    for (int i = 0; i < 32; i++)
#pragma unroll
        for (int c = 0; c < 4; c++) hs[i][c] = 0.f;

    float S = 1.f;

    for (int t = 0; t < TT; t++) {
        const size_t tb = (size_t)b * TT + t;
        const float* qp  = d_qbuf + tb * KEY_DIM + h * KK + j * 32;
        const float* k0p = d_kbuf + tb * (KEY_DIM * NHH) + h * KK + j * 32;
        const float* k1p = k0p + HH * KK;
        const float* v0p = d_vbuf + tb * (VAL_DIM * NHH) + h * VV + vbase;
        const float* v1p = v0p + HH * VV;
        const float eg = expf(d_gbuf[tb * HH + h]);
        const float b0 = d_betabuf[tb * 12 + h];
        const float b1 = d_betabuf[tb * 12 + 6 + h];

        S *= eg;
        if (S < 1e-12f) {     // uniform across CTA (same chain)
#pragma unroll
            for (int i = 0; i < 32; i++)
#pragma unroll
                for (int c = 0; c < 4; c++) hs[i][c] *= S;
            S = 1.f;
        }

        // ---- householder 0 ----
        float a0[32];
#pragma unroll
        for (int m = 0; m < 8; m++) {
            float4 t4 = *(const float4*)(k0p + 4 * m);
            a0[4 * m + 0] = t4.x; a0[4 * m + 1] = t4.y;
            a0[4 * m + 2] = t4.z; a0[4 * m + 3] = t4.w;
        }
        float4 vv0 = *(const float4*)(v0p + s4);
        float p[4] = {0.f, 0.f, 0.f, 0.f};
#pragma unroll
        for (int i = 0; i < 32; i++)
#pragma unroll
            for (int c = 0; c < 4; c++) p[c] = fmaf(hs[i][c], a0[i], p[c]);
#pragma unroll
        for (int c = 0; c < 4; c++) {
            p[c] += __shfl_xor_sync(0xffffffffu, p[c], 1);
            p[c] += __shfl_xor_sync(0xffffffffu, p[c], 2);
            p[c] += __shfl_xor_sync(0xffffffffu, p[c], 4);
        }
        const float i0 = b0 / S;
        float w0[4];
        w0[0] = (vv0.x - S * p[0]) * i0;
        w0[1] = (vv0.y - S * p[1]) * i0;
        w0[2] = (vv0.z - S * p[2]) * i0;
        w0[3] = (vv0.w - S * p[3]) * i0;
#pragma unroll
        for (int i = 0; i < 32; i++)
#pragma unroll
            for (int c = 0; c < 4; c++) hs[i][c] = fmaf(a0[i], w0[c], hs[i][c]);

        // ---- householder 1 ----
        float a1[32];
#pragma unroll
        for (int m = 0; m < 8; m++) {
            float4 t4 = *(const float4*)(k1p + 4 * m);
            a1[4 * m + 0] = t4.x; a1[4 * m + 1] = t4.y;
            a1[4 * m + 2] = t4.z; a1[4 * m + 3] = t4.w;
        }
        float4 vv1 = *(const float4*)(v1p + s4);
#pragma unroll
        for (int c = 0; c < 4; c++) p[c] = 0.f;
#pragma unroll
        for (int i = 0; i < 32; i++)
#pragma unroll
            for (int c = 0; c < 4; c++) p[c] = fmaf(hs[i][c], a1[i], p[c]);
#pragma unroll
        for (int c = 0; c < 4; c++) {
            p[c] += __shfl_xor_sync(0xffffffffu, p[c], 1);
            p[c] += __shfl_xor_sync(0xffffffffu, p[c], 2);
            p[c] += __shfl_xor_sync(0xffffffffu, p[c], 4);
        }
        const float i1 = b1 / S;
        float w1[4];
        w1[0] = (vv1.x - S * p[0]) * i1;
        w1[1] = (vv1.y - S * p[1]) * i1;
        w1[2] = (vv1.z - S * p[2]) * i1;
        w1[3] = (vv1.w - S * p[3]) * i1;
#pragma unroll
        for (int i = 0; i < 32; i++)
#pragma unroll
            for (int c = 0; c < 4; c++) hs[i][c] = fmaf(a1[i], w1[c], hs[i][c]);

        // ---- output ----
        float qs[32];
#pragma unroll
        for (int m = 0; m < 8; m++) {
            float4 t4 = *(const float4*)(qp + 4 * m);
            qs[4 * m + 0] = t4.x; qs[4 * m + 1] = t4.y;
            qs[4 * m + 2] = t4.z; qs[4 * m + 3] = t4.w;
        }
#pragma unroll
        for (int c = 0; c < 4; c++) p[c] = 0.f;
#pragma unroll
        for (int i = 0; i < 32; i++)
#pragma unroll
            for (int c = 0; c < 4; c++) p[c] = fmaf(hs[i][c], qs[i], p[c]);
#pragma unroll
        for (int c = 0; c < 4; c++) {
            p[c] += __shfl_xor_sync(0xffffffffu, p[c], 1);
            p[c] += __shfl_xor_sync(0xffffffffu, p[c], 2);
            p[c] += __shfl_xor_sync(0xffffffffu, p[c], 4);
        }
        if (j == 0) {
            const float fs = S * 0.0625f;   // 256^-0.5
            float4 o4;
            o4.x = p[0] * fs; o4.y = p[1] * fs; o4.z = p[2] * fs; o4.w = p[3] * fs;
            *(float4*)(d_omid + tb * VAL_DIM + h * VV + vbase + s4) = o4;
        }
    }
}

// ------------- gated RMSNorm over V=512 -> bf16 hi/lo ------------------------
__global__ void __launch_bounds__(256) rmsgate_kernel(const float* __restrict__ wnorm) {
    int warp = (blockIdx.x * blockDim.x + threadIdx.x) >> 5;  // row = (b,t,h)
    int l = threadIdx.x & 31;
    const float* row = d_omid + (size_t)warp * VV;
    const float* gr = d_gatebuf + (size_t)warp * VV;
    float vr[16];
    float s = 0.f;
#pragma unroll
    for (int i = 0; i < 16; i++) {
        vr[i] = row[l + 32 * i];
        s = fmaf(vr[i], vr[i], s);
    }
#pragma unroll
    for (int off = 16; off > 0; off >>= 1) s += __shfl_xor_sync(0xffffffffu, s, off);
    float rinv = rsqrtf(s * (1.f / (float)VV) + 1e-5f);
#pragma unroll
    for (int i = 0; i < 16; i++) {
        int idx = l + 32 * i;
        float gv = gr[idx];
        float sig = 1.f / (1.f + expf(-gv));
        float val = vr[i] * rinv * wnorm[idx] * sig;
        __nv_bfloat16 hh = __float2bfloat16(val);
        d_onhi[(size_t)warp * VV + idx] = hh;
        d_onlo[(size_t)warp * VV + idx] = __float2bfloat16(val - __bfloat162float(hh));
    }
}

// ---------------------------------------------------------------------------
extern "C" void kernel_launch(void* const* d_in, const int* in_sizes, int n_in,
                              void* d_out, int out_size) {
    const float* x = (const float*)d_in[0];
    const float* Wq = (const float*)d_in[1];
    const float* Wk = (const float*)d_in[2];
    const float* Wv = (const float*)d_in[3];
    const float* Wb = (const float*)d_in[4];
    const float* Wa = (const float*)d_in[5];
    const float* A_log = (const float*)d_in[6];
    const float* dt_bias = (const float*)d_in[7];
    const float* Wg = (const float*)d_in[8];
    const float* Wo = (const float*)d_in[9];
    const float* o_norm_w = (const float*)d_in[10];
    float* out = (float*)d_out;

    __nv_bfloat16 *xhi, *xlo, *wqhi, *wqlo, *wkhi, *wklo, *wvhi, *wvlo,
                  *wghi, *wglo, *wohi, *wolo, *onhi, *onlo;
    cudaGetSymbolAddress((void**)&xhi, d_xhi);   cudaGetSymbolAddress((void**)&xlo, d_xlo);
    cudaGetSymbolAddress((void**)&wqhi, d_wqhi); cudaGetSymbolAddress((void**)&wqlo, d_wqlo);
    cudaGetSymbolAddress((void**)&wkhi, d_wkhi); cudaGetSymbolAddress((void**)&wklo, d_wklo);
    cudaGetSymbolAddress((void**)&wvhi, d_wvhi); cudaGetSymbolAddress((void**)&wvlo, d_wvlo);
    cudaGetSymbolAddress((void**)&wghi, d_wghi); cudaGetSymbolAddress((void**)&wglo, d_wglo);
    cudaGetSymbolAddress((void**)&wohi, d_wohi); cudaGetSymbolAddress((void**)&wolo, d_wolo);
    cudaGetSymbolAddress((void**)&onhi, d_onhi); cudaGetSymbolAddress((void**)&onlo, d_onlo);

    cudaFuncSetAttribute(qkvg_gemm, cudaFuncAttributeMaxDynamicSharedMemorySize, GEMM_SMEM);
    cudaFuncSetAttribute(gemm_out, cudaFuncAttributeMaxDynamicSharedMemorySize, GEMM_SMEM);

    // fp32 -> bf16 hi/lo splits
    auto split = [&](const float* src, __nv_bfloat16* hi, __nv_bfloat16* lo, int n) {
        int n4 = n / 4;
        split_bf16<<<(n4 + 255) / 256, 256>>>((const float4*)src,
                                              (__nv_bfloat162*)hi, (__nv_bfloat162*)lo, n4);
    };
    split(x, xhi, xlo, NTOK * DD);
    split(Wq, wqhi, wqlo, KEY_DIM * DD);
    split(Wk, wkhi, wklo, KEY_DIM * NHH * DD);
    split(Wv, wvhi, wvlo, VAL_DIM * NHH * DD);
    split(Wg, wghi, wglo, VAL_DIM * DD);
    split(Wo, wohi, wolo, DD * VAL_DIM);

    // beta / g (independent of GEMMs)
    proj_small<<<(NTOK * 18) / 8, 256>>>(x, Wb, Wa, A_log, dt_bias);

    // fused q/k/v/gate projections
    qkvg_gemm<<<dim3(54, 16), 256, GEMM_SMEM>>>();

    // normalize k rows
    knorm_kernel<<<(NTOK * NHH * HH) / 8, 256>>>();

    // sequential recurrence
    recurrence_kernel<<<96, 256>>>();

    // gated RMSNorm -> bf16 hi/lo
    rmsgate_kernel<<<(NTOK * HH) / 8, 256>>>(o_norm_w);

    // output projection
    gemm_out<<<dim3(DD / 256, NTOK / 128), 256, GEMM_SMEM>>>(onhi, onlo, wohi, wolo, out, VAL_DIM, DD);
}

// round 9
// speedup vs baseline: 1.9080x; 1.0000x over previous
#include <cuda_runtime.h>
#include <cuda_bf16.h>
#include <math.h>
#include <stdint.h>

// Problem constants
#define BB 4
#define TT 512
#define DD 2048
#define HH 6
#define KK 256
#define VV 512
#define NHH 2
#define NTOK (BB * TT)          // 2048
#define KEY_DIM (HH * KK)       // 1536
#define VAL_DIM (HH * VV)       // 3072

// ---------------- scratch (static device globals; no allocation) -------------
__device__ float d_qbuf[NTOK * KEY_DIM];
__device__ float d_kbuf[NTOK * KEY_DIM * NHH];
__device__ float d_vbuf[NTOK * VAL_DIM * NHH];
__device__ float d_gatebuf[NTOK * VAL_DIM];
__device__ float d_betabuf[NTOK * NHH * HH];
__device__ float d_gbuf[NTOK * HH];
__device__ float d_omid[NTOK * VAL_DIM];

// bf16 split buffers (hi/lo)
__device__ __nv_bfloat16 d_xhi[NTOK * DD],  d_xlo[NTOK * DD];
__device__ __nv_bfloat16 d_wqhi[KEY_DIM * DD], d_wqlo[KEY_DIM * DD];
__device__ __nv_bfloat16 d_wkhi[KEY_DIM * NHH * DD], d_wklo[KEY_DIM * NHH * DD];
__device__ __nv_bfloat16 d_wvhi[VAL_DIM * NHH * DD], d_wvlo[VAL_DIM * NHH * DD];
__device__ __nv_bfloat16 d_wghi[VAL_DIM * DD], d_wglo[VAL_DIM * DD];
__device__ __nv_bfloat16 d_wohi[DD * VAL_DIM], d_wolo[DD * VAL_DIM];
__device__ __nv_bfloat16 d_onhi[NTOK * VAL_DIM], d_onlo[NTOK * VAL_DIM];

// =================== helpers =================================================
#define CP_ASYNC16(dst, src) \
    asm volatile("cp.async.cg.shared.global [%0], [%1], 16;" :: "r"(dst), "l"(src))
#define CP_COMMIT() asm volatile("cp.async.commit_group;" ::: "memory")

__device__ __forceinline__ uint32_t smem_u32(const void* p) {
    uint32_t a;
    asm("{ .reg .u64 t; cvta.to.shared.u64 t, %1; cvt.u32.u64 %0, t; }" : "=r"(a) : "l"(p));
    return a;
}

__device__ __forceinline__ void mma16816(float* c, const uint32_t* a, const uint32_t* b) {
    asm volatile(
        "mma.sync.aligned.m16n8k16.row.col.f32.bf16.bf16.f32 "
        "{%0,%1,%2,%3}, {%4,%5,%6,%7}, {%8,%9}, {%0,%1,%2,%3};"
        : "+f"(c[0]), "+f"(c[1]), "+f"(c[2]), "+f"(c[3])
        : "r"(a[0]), "r"(a[1]), "r"(a[2]), "r"(a[3]), "r"(b[0]), "r"(b[1]));
}

// =================== fp32 -> bf16 hi/lo split ================================
__global__ void __launch_bounds__(256) split_bf16(const float4* __restrict__ src,
                                                  __nv_bfloat162* __restrict__ hi,
                                                  __nv_bfloat162* __restrict__ lo,
                                                  int n4) {
    int i = blockIdx.x * blockDim.x + threadIdx.x;
    if (i >= n4) return;
    float4 a = src[i];
    __nv_bfloat16 h0 = __float2bfloat16(a.x);
    __nv_bfloat16 h1 = __float2bfloat16(a.y);
    __nv_bfloat16 h2 = __float2bfloat16(a.z);
    __nv_bfloat16 h3 = __float2bfloat16(a.w);
    hi[2 * i + 0] = __nv_bfloat162(h0, h1);
    hi[2 * i + 1] = __nv_bfloat162(h2, h3);
    lo[2 * i + 0] = __nv_bfloat162(__float2bfloat16(a.x - __bfloat162float(h0)),
                                   __float2bfloat16(a.y - __bfloat162float(h1)));
    lo[2 * i + 1] = __nv_bfloat162(__float2bfloat16(a.z - __bfloat162float(h2)),
                                   __float2bfloat16(a.w - __bfloat162float(h3)));
}

// =================== mma.sync bf16 GEMM body =================================
// Block tile 128(M) x 256(N), BK=32, 8 warps (2x4), warp tile 64x64.
// 3-stage cp.async pipeline. 3-term split: D += Ah*Bh + Al*Bh + Ah*Bl.
// Pointers are pre-offset to the block origin. ROWB = 80 bytes.
#define ST_A 10240
#define ST_B 20480
#define STAGE_B 61440
#define GEMM_SMEM (3 * STAGE_B)      // 184320

__device__ __forceinline__ void gemm_body(
    const __nv_bfloat16* __restrict__ Ahi, const __nv_bfloat16* __restrict__ Alo,
    const __nv_bfloat16* __restrict__ Bhi, const __nv_bfloat16* __restrict__ Blo,
    float* __restrict__ Cblk, int Kd, int ldC, int act, char* smem)
{
    const uint32_t sb = smem_u32(smem);
    const int tid = threadIdx.x;
    const int lane = tid & 31;
    const int wid = tid >> 5;
    const int wm = wid >> 2;          // 0..1
    const int wn = wid & 3;           // 0..3
    const int g = lane >> 2;          // 0..7
    const int q4b = (lane & 3) << 2;  // byte offset in k
    const int NS = Kd / 32;

    auto load_stage = [&](int s, int buf) {
        const uint32_t base = sb + (uint32_t)buf * STAGE_B;
        const int k0 = s * 32;
#pragma unroll
        for (int i = 0; i < 12; i++) {
            int c = tid + i * 256;    // 0..3071
            uint32_t dst;
            const __nv_bfloat16* src;
            if (c < 1024) {           // A hi/lo: 128 rows x 4 chunks
                int half = c >> 9, idx = c & 511, row = idx >> 2, kc = idx & 3;
                dst = base + (uint32_t)half * ST_A + (uint32_t)row * 80u + (uint32_t)kc * 16u;
                src = (half ? Alo : Ahi) + (size_t)row * Kd + k0 + kc * 8;
            } else {                  // B hi/lo: 256 rows x 4 chunks
                int cb = c - 1024, half = cb >> 10, idx = cb & 1023, row = idx >> 2, kc = idx & 3;
                dst = base + 2u * ST_A + (uint32_t)half * ST_B + (uint32_t)row * 80u + (uint32_t)kc * 16u;
                src = (half ? Blo : Bhi) + (size_t)row * Kd + k0 + kc * 8;
            }
            CP_ASYNC16(dst, (const char*)src);
        }
        CP_COMMIT();
    };

    float acc[4][8][4];
#pragma unroll
    for (int mi = 0; mi < 4; mi++)
#pragma unroll
        for (int ni = 0; ni < 8; ni++)
#pragma unroll
            for (int r = 0; r < 4; r++) acc[mi][ni][r] = 0.f;

    load_stage(0, 0);
    load_stage(1, 1);

    int buf = 0;
    for (int s = 0; s < NS; s++) {
        if (s + 1 < NS) {
            asm volatile("cp.async.wait_group 1;" ::: "memory");
        } else {
            asm volatile("cp.async.wait_group 0;" ::: "memory");
        }
        __syncthreads();

        const char* st = smem + buf * STAGE_B;
#pragma unroll
        for (int ks = 0; ks < 2; ks++) {
            const int kb = ks * 32 + q4b;
            uint32_t ah[4][4], al[4][4], bb[8][2];
            // A-hi frags
#pragma unroll
            for (int mi = 0; mi < 4; mi++) {
                const char* p = st + (wm * 64 + mi * 16 + g) * 80 + kb;
                ah[mi][0] = *(const uint32_t*)p;
                ah[mi][1] = *(const uint32_t*)(p + 8 * 80);
                ah[mi][2] = *(const uint32_t*)(p + 16);
                ah[mi][3] = *(const uint32_t*)(p + 8 * 80 + 16);
            }
            // B-hi frags
#pragma unroll
            for (int ni = 0; ni < 8; ni++) {
                const char* p = st + 2 * ST_A + (wn * 64 + ni * 8 + g) * 80 + kb;
                bb[ni][0] = *(const uint32_t*)p;
                bb[ni][1] = *(const uint32_t*)(p + 16);
            }
#pragma unroll
            for (int mi = 0; mi < 4; mi++)
#pragma unroll
                for (int ni = 0; ni < 8; ni++) mma16816(acc[mi][ni], ah[mi], bb[ni]);
            // A-lo frags, multiply with B-hi
#pragma unroll
            for (int mi = 0; mi < 4; mi++) {
                const char* p = st + ST_A + (wm * 64 + mi * 16 + g) * 80 + kb;
                al[mi][0] = *(const uint32_t*)p;
                al[mi][1] = *(const uint32_t*)(p + 8 * 80);
                al[mi][2] = *(const uint32_t*)(p + 16);
                al[mi][3] = *(const uint32_t*)(p + 8 * 80 + 16);
            }
#pragma unroll
            for (int mi = 0; mi < 4; mi++)
#pragma unroll
                for (int ni = 0; ni < 8; ni++) mma16816(acc[mi][ni], al[mi], bb[ni]);
            // B-lo frags (reuse bb), multiply with A-hi
#pragma unroll
            for (int ni = 0; ni < 8; ni++) {
                const char* p = st + 2 * ST_A + ST_B + (wn * 64 + ni * 8 + g) * 80 + kb;
                bb[ni][0] = *(const uint32_t*)p;
                bb[ni][1] = *(const uint32_t*)(p + 16);
            }
#pragma unroll
            for (int mi = 0; mi < 4; mi++)
#pragma unroll
                for (int ni = 0; ni < 8; ni++) mma16816(acc[mi][ni], ah[mi], bb[ni]);
        }
        if (s + 2 < NS) load_stage(s + 2, (s + 2) % 3);
        buf = (buf + 1) % 3;
    }

    // epilogue
#pragma unroll
    for (int mi = 0; mi < 4; mi++) {
        int r0 = wm * 64 + mi * 16 + g;
#pragma unroll
        for (int ni = 0; ni < 8; ni++) {
            int c0 = wn * 64 + ni * 8 + ((lane & 3) << 1);
            float2 lo, hi2;
            lo.x = acc[mi][ni][0];
            lo.y = acc[mi][ni][1];
            hi2.x = acc[mi][ni][2];
            hi2.y = acc[mi][ni][3];
            if (act == 1) {
                lo.x = lo.x / (1.f + expf(-lo.x));
                lo.y = lo.y / (1.f + expf(-lo.y));
                hi2.x = hi2.x / (1.f + expf(-hi2.x));
                hi2.y = hi2.y / (1.f + expf(-hi2.y));
            }
            *(float2*)(Cblk + (size_t)r0 * ldC + c0) = lo;
            *(float2*)(Cblk + (size_t)(r0 + 8) * ldC + c0) = hi2;
        }
    }
}

// fused q/k/v/gate projection: grid (54, 16)
__global__ void __launch_bounds__(256, 1) qkvg_gemm() {
    extern __shared__ __align__(128) char smem[];
    const int nb = blockIdx.x;
    const int mb = blockIdx.y;
    const __nv_bfloat16 *Bhi, *Blo;
    float* C;
    int ldC, act;
    if (nb < 6) {
        Bhi = d_wqhi + (size_t)nb * 256 * DD;  Blo = d_wqlo + (size_t)nb * 256 * DD;
        C = d_qbuf + nb * 256;  ldC = KEY_DIM;  act = 1;
    } else if (nb < 18) {
        int t = nb - 6;
        Bhi = d_wkhi + (size_t)t * 256 * DD;   Blo = d_wklo + (size_t)t * 256 * DD;
        C = d_kbuf + t * 256;   ldC = KEY_DIM * NHH;  act = 1;
    } else if (nb < 42) {
        int t = nb - 18;
        Bhi = d_wvhi + (size_t)t * 256 * DD;   Blo = d_wvlo + (size_t)t * 256 * DD;
        C = d_vbuf + t * 256;   ldC = VAL_DIM * NHH;  act = 1;
    } else {
        int t = nb - 42;
        Bhi = d_wghi + (size_t)t * 256 * DD;   Blo = d_wglo + (size_t)t * 256 * DD;
        C = d_gatebuf + t * 256;  ldC = VAL_DIM;  act = 0;
    }
    gemm_body(d_xhi + (size_t)mb * 128 * DD, d_xlo + (size_t)mb * 128 * DD,
              Bhi, Blo, C + (size_t)mb * 128 * ldC, DD, ldC, act, smem);
}

// generic GEMM (used for output projection): grid (N/256, M/128)
__global__ void __launch_bounds__(256, 1) gemm_out(
    const __nv_bfloat16* __restrict__ Ahi, const __nv_bfloat16* __restrict__ Alo,
    const __nv_bfloat16* __restrict__ Bhi, const __nv_bfloat16* __restrict__ Blo,
    float* __restrict__ C, int Kd, int N) {
    extern __shared__ __align__(128) char smem[];
    gemm_body(Ahi + (size_t)blockIdx.y * 128 * Kd, Alo + (size_t)blockIdx.y * 128 * Kd,
              Bhi + (size_t)blockIdx.x * 256 * Kd, Blo + (size_t)blockIdx.x * 256 * Kd,
              C + (size_t)blockIdx.y * 128 * N + blockIdx.x * 256, Kd, N, 0, smem);
}

// ------------- small projections: beta (12) and g (6) per token --------------
__global__ void __launch_bounds__(256) proj_small(const float* __restrict__ x,
                                                  const float* __restrict__ Wb,
                                                  const float* __restrict__ Wa,
                                                  const float* __restrict__ A_log,
                                                  const float* __restrict__ dt_bias) {
    int warp = (blockIdx.x * blockDim.x + threadIdx.x) >> 5;
    int l = threadIdx.x & 31;
    int t = warp / 18;
    int o = warp % 18;
    const float* xr = x + (size_t)t * DD;
    const float* wr = (o < 12) ? (Wb + (size_t)o * DD) : (Wa + (size_t)(o - 12) * DD);
    float s = 0.f;
    for (int i = l; i < DD; i += 32) s = fmaf(xr[i], wr[i], s);
#pragma unroll
    for (int off = 16; off > 0; off >>= 1) s += __shfl_xor_sync(0xffffffffu, s, off);
    if (l == 0) {
        if (o < 12) {
            d_betabuf[(size_t)t * 12 + o] = 2.f / (1.f + expf(-s));
        } else {
            int h = o - 12;
            float z = s + dt_bias[h];
            float sp = (z > 20.f) ? z : log1pf(expf(z));
            d_gbuf[(size_t)t * 6 + h] = -expf(A_log[h]) * sp;
        }
    }
}

// ------------- normalize k rows (length 256) in place ------------------------
__global__ void __launch_bounds__(256) knorm_kernel() {
    int warp = (blockIdx.x * blockDim.x + threadIdx.x) >> 5;
    int l = threadIdx.x & 31;
    float* row = d_kbuf + (size_t)warp * KK;
    float vr[8];
    float s = 0.f;
#pragma unroll
    for (int i = 0; i < 8; i++) {
        vr[i] = row[l + 32 * i];
        s = fmaf(vr[i], vr[i], s);
    }
#pragma unroll
    for (int off = 16; off > 0; off >>= 1) s += __shfl_xor_sync(0xffffffffu, s, off);
    float inv = 1.f / fmaxf(sqrtf(s), 1e-12f);
#pragma unroll
    for (int i = 0; i < 8; i++) row[l + 32 * i] = vr[i] * inv;
}

// ------------- recurrence: 96 persistent CTAs, state in registers ------------
// CTA = (bh, vchunk of 128 cols). Warp w: 16 cols. Lane l: k-slice j = l&7
// (32 consecutive k), v sub-block s4 = (l>>3)*4 (4 cols). Reduction over k =
// in-thread 32 + 3 shuffles across the 8-lane k-group.
// Decay folded into scalar carry S (h_true = S * hs), renormalized when small.
__global__ void __launch_bounds__(256, 1) recurrence_kernel() {
    const int cta = blockIdx.x;
    const int bh = cta >> 2;
    const int vc = cta & 3;
    const int b = bh / HH;
    const int h = bh % HH;
    const int w = threadIdx.x >> 5;
    const int l = threadIdx.x & 31;
    const int j = l & 7;
    const int s4 = (l >> 3) << 2;
    const int vbase = vc * 128 + w * 16;

    float hs[32][4];
#pragma unroll
    for (int i = 0; i < 32; i++)
#pragma unroll
        for (int c = 0; c < 4; c++) hs[i][c] = 0.f;

    float S = 1.f;

    for (int t = 0; t < TT; t++) {
        const size_t tb = (size_t)b * TT + t;
        const float* qp  = d_qbuf + tb * KEY_DIM + h * KK + j * 32;
        const float* k0p = d_kbuf + tb * (KEY_DIM * NHH) + h * KK + j * 32;
        const float* k1p = k0p + HH * KK;
        const float* v0p = d_vbuf + tb * (VAL_DIM * NHH) + h * VV + vbase;
        const float* v1p = v0p + HH * VV;
        const float eg = expf(d_gbuf[tb * HH + h]);
        const float b0 = d_betabuf[tb * 12 + h];
        const float b1 = d_betabuf[tb * 12 + 6 + h];

        S *= eg;
        if (S < 1e-12f) {     // uniform across CTA (same chain)
#pragma unroll
            for (int i = 0; i < 32; i++)
#pragma unroll
                for (int c = 0; c < 4; c++) hs[i][c] *= S;
            S = 1.f;
        }

        // ---- householder 0 ----
        float a0[32];
#pragma unroll
        for (int m = 0; m < 8; m++) {
            float4 t4 = *(const float4*)(k0p + 4 * m);
            a0[4 * m + 0] = t4.x; a0[4 * m + 1] = t4.y;
            a0[4 * m + 2] = t4.z; a0[4 * m + 3] = t4.w;
        }
        float4 vv0 = *(const float4*)(v0p + s4);
        float p[4] = {0.f, 0.f, 0.f, 0.f};
#pragma unroll
        for (int i = 0; i < 32; i++)
#pragma unroll
            for (int c = 0; c < 4; c++) p[c] = fmaf(hs[i][c], a0[i], p[c]);
#pragma unroll
        for (int c = 0; c < 4; c++) {
            p[c] += __shfl_xor_sync(0xffffffffu, p[c], 1);
            p[c] += __shfl_xor_sync(0xffffffffu, p[c], 2);
            p[c] += __shfl_xor_sync(0xffffffffu, p[c], 4);
        }
        const float i0 = b0 / S;
        float w0[4];
        w0[0] = (vv0.x - S * p[0]) * i0;
        w0[1] = (vv0.y - S * p[1]) * i0;
        w0[2] = (vv0.z - S * p[2]) * i0;
        w0[3] = (vv0.w - S * p[3]) * i0;
#pragma unroll
        for (int i = 0; i < 32; i++)
#pragma unroll
            for (int c = 0; c < 4; c++) hs[i][c] = fmaf(a0[i], w0[c], hs[i][c]);

        // ---- householder 1 ----
        float a1[32];
#pragma unroll
        for (int m = 0; m < 8; m++) {
            float4 t4 = *(const float4*)(k1p + 4 * m);
            a1[4 * m + 0] = t4.x; a1[4 * m + 1] = t4.y;
            a1[4 * m + 2] = t4.z; a1[4 * m + 3] = t4.w;
        }
        float4 vv1 = *(const float4*)(v1p + s4);
#pragma unroll
        for (int c = 0; c < 4; c++) p[c] = 0.f;
#pragma unroll
        for (int i = 0; i < 32; i++)
#pragma unroll
            for (int c = 0; c < 4; c++) p[c] = fmaf(hs[i][c], a1[i], p[c]);
#pragma unroll
        for (int c = 0; c < 4; c++) {
            p[c] += __shfl_xor_sync(0xffffffffu, p[c], 1);
            p[c] += __shfl_xor_sync(0xffffffffu, p[c], 2);
            p[c] += __shfl_xor_sync(0xffffffffu, p[c], 4);
        }
        const float i1 = b1 / S;
        float w1[4];
        w1[0] = (vv1.x - S * p[0]) * i1;
        w1[1] = (vv1.y - S * p[1]) * i1;
        w1[2] = (vv1.z - S * p[2]) * i1;
        w1[3] = (vv1.w - S * p[3]) * i1;
#pragma unroll
        for (int i = 0; i < 32; i++)
#pragma unroll
            for (int c = 0; c < 4; c++) hs[i][c] = fmaf(a1[i], w1[c], hs[i][c]);

        // ---- output ----
        float qs[32];
#pragma unroll
        for (int m = 0; m < 8; m++) {
            float4 t4 = *(const float4*)(qp + 4 * m);
            qs[4 * m + 0] = t4.x; qs[4 * m + 1] = t4.y;
            qs[4 * m + 2] = t4.z; qs[4 * m + 3] = t4.w;
        }
#pragma unroll
        for (int c = 0; c < 4; c++) p[c] = 0.f;
#pragma unroll
        for (int i = 0; i < 32; i++)
#pragma unroll
            for (int c = 0; c < 4; c++) p[c] = fmaf(hs[i][c], qs[i], p[c]);
#pragma unroll
        for (int c = 0; c < 4; c++) {
            p[c] += __shfl_xor_sync(0xffffffffu, p[c], 1);
            p[c] += __shfl_xor_sync(0xffffffffu, p[c], 2);
            p[c] += __shfl_xor_sync(0xffffffffu, p[c], 4);
        }
        if (j == 0) {
            const float fs = S * 0.0625f;   // 256^-0.5
            float4 o4;
            o4.x = p[0] * fs; o4.y = p[1] * fs; o4.z = p[2] * fs; o4.w = p[3] * fs;
            *(float4*)(d_omid + tb * VAL_DIM + h * VV + vbase + s4) = o4;
        }
    }
}

// ------------- gated RMSNorm over V=512 -> bf16 hi/lo ------------------------
__global__ void __launch_bounds__(256) rmsgate_kernel(const float* __restrict__ wnorm) {
    int warp = (blockIdx.x * blockDim.x + threadIdx.x) >> 5;  // row = (b,t,h)
    int l = threadIdx.x & 31;
    const float* row = d_omid + (size_t)warp * VV;
    const float* gr = d_gatebuf + (size_t)warp * VV;
    float vr[16];
    float s = 0.f;
#pragma unroll
    for (int i = 0; i < 16; i++) {
        vr[i] = row[l + 32 * i];
        s = fmaf(vr[i], vr[i], s);
    }
#pragma unroll
    for (int off = 16; off > 0; off >>= 1) s += __shfl_xor_sync(0xffffffffu, s, off);
    float rinv = rsqrtf(s * (1.f / (float)VV) + 1e-5f);
#pragma unroll
    for (int i = 0; i < 16; i++) {
        int idx = l + 32 * i;
        float gv = gr[idx];
        float sig = 1.f / (1.f + expf(-gv));
        float val = vr[i] * rinv * wnorm[idx] * sig;
        __nv_bfloat16 hh = __float2bfloat16(val);
        d_onhi[(size_t)warp * VV + idx] = hh;
        d_onlo[(size_t)warp * VV + idx] = __float2bfloat16(val - __bfloat162float(hh));
    }
}

// ---------------------------------------------------------------------------
extern "C" void kernel_launch(void* const* d_in, const int* in_sizes, int n_in,
                              void* d_out, int out_size) {
    const float* x = (const float*)d_in[0];
    const float* Wq = (const float*)d_in[1];
    const float* Wk = (const float*)d_in[2];
    const float* Wv = (const float*)d_in[3];
    const float* Wb = (const float*)d_in[4];
    const float* Wa = (const float*)d_in[5];
    const float* A_log = (const float*)d_in[6];
    const float* dt_bias = (const float*)d_in[7];
    const float* Wg = (const float*)d_in[8];
    const float* Wo = (const float*)d_in[9];
    const float* o_norm_w = (const float*)d_in[10];
    float* out = (float*)d_out;

    __nv_bfloat16 *xhi, *xlo, *wqhi, *wqlo, *wkhi, *wklo, *wvhi, *wvlo,
                  *wghi, *wglo, *wohi, *wolo, *onhi, *onlo;
    cudaGetSymbolAddress((void**)&xhi, d_xhi);   cudaGetSymbolAddress((void**)&xlo, d_xlo);
    cudaGetSymbolAddress((void**)&wqhi, d_wqhi); cudaGetSymbolAddress((void**)&wqlo, d_wqlo);
    cudaGetSymbolAddress((void**)&wkhi, d_wkhi); cudaGetSymbolAddress((void**)&wklo, d_wklo);
    cudaGetSymbolAddress((void**)&wvhi, d_wvhi); cudaGetSymbolAddress((void**)&wvlo, d_wvlo);
    cudaGetSymbolAddress((void**)&wghi, d_wghi); cudaGetSymbolAddress((void**)&wglo, d_wglo);
    cudaGetSymbolAddress((void**)&wohi, d_wohi); cudaGetSymbolAddress((void**)&wolo, d_wolo);
    cudaGetSymbolAddress((void**)&onhi, d_onhi); cudaGetSymbolAddress((void**)&onlo, d_onlo);

    cudaFuncSetAttribute(qkvg_gemm, cudaFuncAttributeMaxDynamicSharedMemorySize, GEMM_SMEM);
    cudaFuncSetAttribute(gemm_out, cudaFuncAttributeMaxDynamicSharedMemorySize, GEMM_SMEM);

    // fp32 -> bf16 hi/lo splits
    auto split = [&](const float* src, __nv_bfloat16* hi, __nv_bfloat16* lo, int n) {
        int n4 = n / 4;
        split_bf16<<<(n4 + 255) / 256, 256>>>((const float4*)src,
                                              (__nv_bfloat162*)hi, (__nv_bfloat162*)lo, n4);
    };
    split(x, xhi, xlo, NTOK * DD);
    split(Wq, wqhi, wqlo, KEY_DIM * DD);
    split(Wk, wkhi, wklo, KEY_DIM * NHH * DD);
    split(Wv, wvhi, wvlo, VAL_DIM * NHH * DD);
    split(Wg, wghi, wglo, VAL_DIM * DD);
    split(Wo, wohi, wolo, DD * VAL_DIM);

    // beta / g (independent of GEMMs)
    proj_small<<<(NTOK * 18) / 8, 256>>>(x, Wb, Wa, A_log, dt_bias);

    // fused q/k/v/gate projections
    qkvg_gemm<<<dim3(54, 16), 256, GEMM_SMEM>>>();

    // normalize k rows
    knorm_kernel<<<(NTOK * NHH * HH) / 8, 256>>>();

    // sequential recurrence
    recurrence_kernel<<<96, 256>>>();

    // gated RMSNorm -> bf16 hi/lo
    rmsgate_kernel<<<(NTOK * HH) / 8, 256>>>(o_norm_w);

    // output projection
    gemm_out<<<dim3(DD / 256, NTOK / 128), 256, GEMM_SMEM>>>(onhi, onlo, wohi, wolo, out, VAL_DIM, DD);
}

// round 10
// speedup vs baseline: 1.9094x; 1.0007x over previous
#include <cuda_runtime.h>
#include <cuda_bf16.h>
#include <math.h>
#include <stdint.h>

// Problem constants
#define BB 4
#define TT 512
#define DD 2048
#define HH 6
#define KK 256
#define VV 512
#define NHH 2
#define NTOK (BB * TT)          // 2048
#define KEY_DIM (HH * KK)       // 1536
#define VAL_DIM (HH * VV)       // 3072

// ---------------- scratch (static device globals; no allocation) -------------
__device__ float d_qbuf[NTOK * KEY_DIM];
__device__ float d_kbuf[NTOK * KEY_DIM * NHH];
__device__ float d_vbuf[NTOK * VAL_DIM * NHH];
__device__ float d_gatebuf[NTOK * VAL_DIM];
__device__ float d_betabuf[NTOK * NHH * HH];
__device__ float d_gbuf[NTOK * HH];
__device__ float d_omid[NTOK * VAL_DIM];

// bf16 split buffers (hi/lo)
__device__ __nv_bfloat16 d_xhi[NTOK * DD],  d_xlo[NTOK * DD];
__device__ __nv_bfloat16 d_wqhi[KEY_DIM * DD], d_wqlo[KEY_DIM * DD];
__device__ __nv_bfloat16 d_wkhi[KEY_DIM * NHH * DD], d_wklo[KEY_DIM * NHH * DD];
__device__ __nv_bfloat16 d_wvhi[VAL_DIM * NHH * DD], d_wvlo[VAL_DIM * NHH * DD];
__device__ __nv_bfloat16 d_wghi[VAL_DIM * DD], d_wglo[VAL_DIM * DD];
__device__ __nv_bfloat16 d_wohi[DD * VAL_DIM], d_wolo[DD * VAL_DIM];
__device__ __nv_bfloat16 d_onhi[NTOK * VAL_DIM], d_onlo[NTOK * VAL_DIM];

// =================== helpers =================================================
#define CP_ASYNC16(dst, src) \
    asm volatile("cp.async.cg.shared.global [%0], [%1], 16;" :: "r"(dst), "l"(src))
#define CP_COMMIT() asm volatile("cp.async.commit_group;" ::: "memory")

__device__ __forceinline__ uint32_t smem_u32(const void* p) {
    uint32_t a;
    asm("{ .reg .u64 t; cvta.to.shared.u64 t, %1; cvt.u32.u64 %0, t; }" : "=r"(a) : "l"(p));
    return a;
}

__device__ __forceinline__ void mma16816(float* c, const uint32_t* a, const uint32_t* b) {
    asm volatile(
        "mma.sync.aligned.m16n8k16.row.col.f32.bf16.bf16.f32 "
        "{%0,%1,%2,%3}, {%4,%5,%6,%7}, {%8,%9}, {%0,%1,%2,%3};"
        : "+f"(c[0]), "+f"(c[1]), "+f"(c[2]), "+f"(c[3])
        : "r"(a[0]), "r"(a[1]), "r"(a[2]), "r"(a[3]), "r"(b[0]), "r"(b[1]));
}

// =================== fp32 -> bf16 hi/lo split ================================
__global__ void __launch_bounds__(256) split_bf16(const float4* __restrict__ src,
                                                  __nv_bfloat162* __restrict__ hi,
                                                  __nv_bfloat162* __restrict__ lo,
                                                  int n4) {
    int i = blockIdx.x * blockDim.x + threadIdx.x;
    if (i >= n4) return;
    float4 a = src[i];
    __nv_bfloat16 h0 = __float2bfloat16(a.x);
    __nv_bfloat16 h1 = __float2bfloat16(a.y);
    __nv_bfloat16 h2 = __float2bfloat16(a.z);
    __nv_bfloat16 h3 = __float2bfloat16(a.w);
    hi[2 * i + 0] = __nv_bfloat162(h0, h1);
    hi[2 * i + 1] = __nv_bfloat162(h2, h3);
    lo[2 * i + 0] = __nv_bfloat162(__float2bfloat16(a.x - __bfloat162float(h0)),
                                   __float2bfloat16(a.y - __bfloat162float(h1)));
    lo[2 * i + 1] = __nv_bfloat162(__float2bfloat16(a.z - __bfloat162float(h2)),
                                   __float2bfloat16(a.w - __bfloat162float(h3)));
}

// =================== mma.sync bf16 GEMM body =================================
// Block tile 128(M) x 256(N), BK=32, 8 warps (2x4), warp tile 64x64.
// 3-stage cp.async pipeline. 3-term split: D += Ah*Bh + Al*Bh + Ah*Bl.
// Pointers are pre-offset to the block origin. ROWB = 80 bytes.
#define ST_A 10240
#define ST_B 20480
#define STAGE_B 61440
#define GEMM_SMEM (3 * STAGE_B)      // 184320

__device__ __forceinline__ void gemm_body(
    const __nv_bfloat16* __restrict__ Ahi, const __nv_bfloat16* __restrict__ Alo,
    const __nv_bfloat16* __restrict__ Bhi, const __nv_bfloat16* __restrict__ Blo,
    float* __restrict__ Cblk, int Kd, int ldC, int act, char* smem)
{
    const uint32_t sb = smem_u32(smem);
    const int tid = threadIdx.x;
    const int lane = tid & 31;
    const int wid = tid >> 5;
    const int wm = wid >> 2;          // 0..1
    const int wn = wid & 3;           // 0..3
    const int g = lane >> 2;          // 0..7
    const int q4b = (lane & 3) << 2;  // byte offset in k
    const int NS = Kd / 32;

    auto load_stage = [&](int s, int buf) {
        const uint32_t base = sb + (uint32_t)buf * STAGE_B;
        const int k0 = s * 32;
#pragma unroll
        for (int i = 0; i < 12; i++) {
            int c = tid + i * 256;    // 0..3071
            uint32_t dst;
            const __nv_bfloat16* src;
            if (c < 1024) {           // A hi/lo: 128 rows x 4 chunks
                int half = c >> 9, idx = c & 511, row = idx >> 2, kc = idx & 3;
                dst = base + (uint32_t)half * ST_A + (uint32_t)row * 80u + (uint32_t)kc * 16u;
                src = (half ? Alo : Ahi) + (size_t)row * Kd + k0 + kc * 8;
            } else {                  // B hi/lo: 256 rows x 4 chunks
                int cb = c - 1024, half = cb >> 10, idx = cb & 1023, row = idx >> 2, kc = idx & 3;
                dst = base + 2u * ST_A + (uint32_t)half * ST_B + (uint32_t)row * 80u + (uint32_t)kc * 16u;
                src = (half ? Blo : Bhi) + (size_t)row * Kd + k0 + kc * 8;
            }
            CP_ASYNC16(dst, (const char*)src);
        }
        CP_COMMIT();
    };

    float acc[4][8][4];
#pragma unroll
    for (int mi = 0; mi < 4; mi++)
#pragma unroll
        for (int ni = 0; ni < 8; ni++)
#pragma unroll
            for (int r = 0; r < 4; r++) acc[mi][ni][r] = 0.f;

    load_stage(0, 0);
    load_stage(1, 1);

    int buf = 0;
    for (int s = 0; s < NS; s++) {
        if (s + 1 < NS) {
            asm volatile("cp.async.wait_group 1;" ::: "memory");
        } else {
            asm volatile("cp.async.wait_group 0;" ::: "memory");
        }
        __syncthreads();

        const char* st = smem + buf * STAGE_B;
#pragma unroll
        for (int ks = 0; ks < 2; ks++) {
            const int kb = ks * 32 + q4b;
            uint32_t ah[4][4], al[4][4], bb[8][2];
            // A-hi frags
#pragma unroll
            for (int mi = 0; mi < 4; mi++) {
                const char* p = st + (wm * 64 + mi * 16 + g) * 80 + kb;
                ah[mi][0] = *(const uint32_t*)p;
                ah[mi][1] = *(const uint32_t*)(p + 8 * 80);
                ah[mi][2] = *(const uint32_t*)(p + 16);
                ah[mi][3] = *(const uint32_t*)(p + 8 * 80 + 16);
            }
            // B-hi frags
#pragma unroll
            for (int ni = 0; ni < 8; ni++) {
                const char* p = st + 2 * ST_A + (wn * 64 + ni * 8 + g) * 80 + kb;
                bb[ni][0] = *(const uint32_t*)p;
                bb[ni][1] = *(const uint32_t*)(p + 16);
            }
#pragma unroll
            for (int mi = 0; mi < 4; mi++)
#pragma unroll
                for (int ni = 0; ni < 8; ni++) mma16816(acc[mi][ni], ah[mi], bb[ni]);
            // A-lo frags, multiply with B-hi
#pragma unroll
            for (int mi = 0; mi < 4; mi++) {
                const char* p = st + ST_A + (wm * 64 + mi * 16 + g) * 80 + kb;
                al[mi][0] = *(const uint32_t*)p;
                al[mi][1] = *(const uint32_t*)(p + 8 * 80);
                al[mi][2] = *(const uint32_t*)(p + 16);
                al[mi][3] = *(const uint32_t*)(p + 8 * 80 + 16);
            }
#pragma unroll
            for (int mi = 0; mi < 4; mi++)
#pragma unroll
                for (int ni = 0; ni < 8; ni++) mma16816(acc[mi][ni], al[mi], bb[ni]);
            // B-lo frags (reuse bb), multiply with A-hi
#pragma unroll
            for (int ni = 0; ni < 8; ni++) {
                const char* p = st + 2 * ST_A + ST_B + (wn * 64 + ni * 8 + g) * 80 + kb;
                bb[ni][0] = *(const uint32_t*)p;
                bb[ni][1] = *(const uint32_t*)(p + 16);
            }
#pragma unroll
            for (int mi = 0; mi < 4; mi++)
#pragma unroll
                for (int ni = 0; ni < 8; ni++) mma16816(acc[mi][ni], ah[mi], bb[ni]);
        }
        if (s + 2 < NS) load_stage(s + 2, (s + 2) % 3);
        buf = (buf + 1) % 3;
    }

    // epilogue
#pragma unroll
    for (int mi = 0; mi < 4; mi++) {
        int r0 = wm * 64 + mi * 16 + g;
#pragma unroll
        for (int ni = 0; ni < 8; ni++) {
            int c0 = wn * 64 + ni * 8 + ((lane & 3) << 1);
            float2 lo, hi2;
            lo.x = acc[mi][ni][0];
            lo.y = acc[mi][ni][1];
            hi2.x = acc[mi][ni][2];
            hi2.y = acc[mi][ni][3];
            if (act == 1) {
                lo.x = lo.x / (1.f + expf(-lo.x));
                lo.y = lo.y / (1.f + expf(-lo.y));
                hi2.x = hi2.x / (1.f + expf(-hi2.x));
                hi2.y = hi2.y / (1.f + expf(-hi2.y));
            }
            *(float2*)(Cblk + (size_t)r0 * ldC + c0) = lo;
            *(float2*)(Cblk + (size_t)(r0 + 8) * ldC + c0) = hi2;
        }
    }
}

// fused q/k/v/gate projection: grid (54, 16)
__global__ void __launch_bounds__(256, 1) qkvg_gemm() {
    extern __shared__ __align__(128) char smem[];
    const int nb = blockIdx.x;
    const int mb = blockIdx.y;
    const __nv_bfloat16 *Bhi, *Blo;
    float* C;
    int ldC, act;
    if (nb < 6) {
        Bhi = d_wqhi + (size_t)nb * 256 * DD;  Blo = d_wqlo + (size_t)nb * 256 * DD;
        C = d_qbuf + nb * 256;  ldC = KEY_DIM;  act = 1;
    } else if (nb < 18) {
        int t = nb - 6;
        Bhi = d_wkhi + (size_t)t * 256 * DD;   Blo = d_wklo + (size_t)t * 256 * DD;
        C = d_kbuf + t * 256;   ldC = KEY_DIM * NHH;  act = 1;
    } else if (nb < 42) {
        int t = nb - 18;
        Bhi = d_wvhi + (size_t)t * 256 * DD;   Blo = d_wvlo + (size_t)t * 256 * DD;
        C = d_vbuf + t * 256;   ldC = VAL_DIM * NHH;  act = 1;
    } else {
        int t = nb - 42;
        Bhi = d_wghi + (size_t)t * 256 * DD;   Blo = d_wglo + (size_t)t * 256 * DD;
        C = d_gatebuf + t * 256;  ldC = VAL_DIM;  act = 0;
    }
    gemm_body(d_xhi + (size_t)mb * 128 * DD, d_xlo + (size_t)mb * 128 * DD,
              Bhi, Blo, C + (size_t)mb * 128 * ldC, DD, ldC, act, smem);
}

// generic GEMM (used for output projection): grid (N/256, M/128)
__global__ void __launch_bounds__(256, 1) gemm_out(
    const __nv_bfloat16* __restrict__ Ahi, const __nv_bfloat16* __restrict__ Alo,
    const __nv_bfloat16* __restrict__ Bhi, const __nv_bfloat16* __restrict__ Blo,
    float* __restrict__ C, int Kd, int N) {
    extern __shared__ __align__(128) char smem[];
    gemm_body(Ahi + (size_t)blockIdx.y * 128 * Kd, Alo + (size_t)blockIdx.y * 128 * Kd,
              Bhi + (size_t)blockIdx.x * 256 * Kd, Blo + (size_t)blockIdx.x * 256 * Kd,
              C + (size_t)blockIdx.y * 128 * N + blockIdx.x * 256, Kd, N, 0, smem);
}

// ------------- small projections: beta (12) and g (6) per token --------------
__global__ void __launch_bounds__(256) proj_small(const float* __restrict__ x,
                                                  const float* __restrict__ Wb,
                                                  const float* __restrict__ Wa,
                                                  const float* __restrict__ A_log,
                                                  const float* __restrict__ dt_bias) {
    int warp = (blockIdx.x * blockDim.x + threadIdx.x) >> 5;
    int l = threadIdx.x & 31;
    int t = warp / 18;
    int o = warp % 18;
    const float* xr = x + (size_t)t * DD;
    const float* wr = (o < 12) ? (Wb + (size_t)o * DD) : (Wa + (size_t)(o - 12) * DD);
    float s = 0.f;
    for (int i = l; i < DD; i += 32) s = fmaf(xr[i], wr[i], s);
#pragma unroll
    for (int off = 16; off > 0; off >>= 1) s += __shfl_xor_sync(0xffffffffu, s, off);
    if (l == 0) {
        if (o < 12) {
            d_betabuf[(size_t)t * 12 + o] = 2.f / (1.f + expf(-s));
        } else {
            int h = o - 12;
            float z = s + dt_bias[h];
            float sp = (z > 20.f) ? z : log1pf(expf(z));
            d_gbuf[(size_t)t * 6 + h] = -expf(A_log[h]) * sp;
        }
    }
}

// ------------- normalize k rows (length 256) in place ------------------------
__global__ void __launch_bounds__(256) knorm_kernel() {
    int warp = (blockIdx.x * blockDim.x + threadIdx.x) >> 5;
    int l = threadIdx.x & 31;
    float* row = d_kbuf + (size_t)warp * KK;
    float vr[8];
    float s = 0.f;
#pragma unroll
    for (int i = 0; i < 8; i++) {
        vr[i] = row[l + 32 * i];
        s = fmaf(vr[i], vr[i], s);
    }
#pragma unroll
    for (int off = 16; off > 0; off >>= 1) s += __shfl_xor_sync(0xffffffffu, s, off);
    float inv = 1.f / fmaxf(sqrtf(s), 1e-12f);
#pragma unroll
    for (int i = 0; i < 8; i++) row[l + 32 * i] = vr[i] * inv;
}

// ------------- recurrence: 96 persistent CTAs, state in registers ------------
// CTA = (bh, vchunk of 128 cols). Warp w: 16 cols. Lane l: k-slice j = l&7
// (32 consecutive k), v sub-block s4 = (l>>3)*4 (4 cols). Reduction over k =
// in-thread 32 + 3 shuffles across the 8-lane k-group.
// Decay folded into scalar carry S (h_true = S * hs), renormalized when small.
__global__ void __launch_bounds__(256, 1) recurrence_kernel() {
    const int cta = blockIdx.x;
    const int bh = cta >> 2;
    const int vc = cta & 3;
    const int b = bh / HH;
    const int h = bh % HH;
    const int w = threadIdx.x >> 5;
    const int l = threadIdx.x & 31;
    const int j = l & 7;
    const int s4 = (l >> 3) << 2;
    const int vbase = vc * 128 + w * 16;

    float hs[32][4];
#pragma unroll
    for (int i = 0; i < 32; i++)
#pragma unroll
        for (int c = 0; c < 4; c++) hs[i][c] = 0.f;

    float S = 1.f;

    for (int t = 0; t < TT; t++) {
        const size_t tb = (size_t)b * TT + t;
        const float* qp  = d_qbuf + tb * KEY_DIM + h * KK + j * 32;
        const float* k0p = d_kbuf + tb * (KEY_DIM * NHH) + h * KK + j * 32;
        const float* k1p = k0p + HH * KK;
        const float* v0p = d_vbuf + tb * (VAL_DIM * NHH) + h * VV + vbase;
        const float* v1p = v0p + HH * VV;
        const float eg = expf(d_gbuf[tb * HH + h]);
        const float b0 = d_betabuf[tb * 12 + h];
        const float b1 = d_betabuf[tb * 12 + 6 + h];

        S *= eg;
        if (S < 1e-12f) {     // uniform across CTA (same chain)
#pragma unroll
            for (int i = 0; i < 32; i++)
#pragma unroll
                for (int c = 0; c < 4; c++) hs[i][c] *= S;
            S = 1.f;
        }

        // ---- householder 0 ----
        float a0[32];
#pragma unroll
        for (int m = 0; m < 8; m++) {
            float4 t4 = *(const float4*)(k0p + 4 * m);
            a0[4 * m + 0] = t4.x; a0[4 * m + 1] = t4.y;
            a0[4 * m + 2] = t4.z; a0[4 * m + 3] = t4.w;
        }
        float4 vv0 = *(const float4*)(v0p + s4);
        float p[4] = {0.f, 0.f, 0.f, 0.f};
#pragma unroll
        for (int i = 0; i < 32; i++)
#pragma unroll
            for (int c = 0; c < 4; c++) p[c] = fmaf(hs[i][c], a0[i], p[c]);
#pragma unroll
        for (int c = 0; c < 4; c++) {
            p[c] += __shfl_xor_sync(0xffffffffu, p[c], 1);
            p[c] += __shfl_xor_sync(0xffffffffu, p[c], 2);
            p[c] += __shfl_xor_sync(0xffffffffu, p[c], 4);
        }
        const float i0 = b0 / S;
        float w0[4];
        w0[0] = (vv0.x - S * p[0]) * i0;
        w0[1] = (vv0.y - S * p[1]) * i0;
        w0[2] = (vv0.z - S * p[2]) * i0;
        w0[3] = (vv0.w - S * p[3]) * i0;
#pragma unroll
        for (int i = 0; i < 32; i++)
#pragma unroll
            for (int c = 0; c < 4; c++) hs[i][c] = fmaf(a0[i], w0[c], hs[i][c]);

        // ---- householder 1 ----
        float a1[32];
#pragma unroll
        for (int m = 0; m < 8; m++) {
            float4 t4 = *(const float4*)(k1p + 4 * m);
            a1[4 * m + 0] = t4.x; a1[4 * m + 1] = t4.y;
            a1[4 * m + 2] = t4.z; a1[4 * m + 3] = t4.w;
        }
        float4 vv1 = *(const float4*)(v1p + s4);
#pragma unroll
        for (int c = 0; c < 4; c++) p[c] = 0.f;
#pragma unroll
        for (int i = 0; i < 32; i++)
#pragma unroll
            for (int c = 0; c < 4; c++) p[c] = fmaf(hs[i][c], a1[i], p[c]);
#pragma unroll
        for (int c = 0; c < 4; c++) {
            p[c] += __shfl_xor_sync(0xffffffffu, p[c], 1);
            p[c] += __shfl_xor_sync(0xffffffffu, p[c], 2);
            p[c] += __shfl_xor_sync(0xffffffffu, p[c], 4);
        }
        const float i1 = b1 / S;
        float w1[4];
        w1[0] = (vv1.x - S * p[0]) * i1;
        w1[1] = (vv1.y - S * p[1]) * i1;
        w1[2] = (vv1.z - S * p[2]) * i1;
        w1[3] = (vv1.w - S * p[3]) * i1;
#pragma unroll
        for (int i = 0; i < 32; i++)
#pragma unroll
            for (int c = 0; c < 4; c++) hs[i][c] = fmaf(a1[i], w1[c], hs[i][c]);

        // ---- output ----
        float qs[32];
#pragma unroll
        for (int m = 0; m < 8; m++) {
            float4 t4 = *(const float4*)(qp + 4 * m);
            qs[4 * m + 0] = t4.x; qs[4 * m + 1] = t4.y;
            qs[4 * m + 2] = t4.z; qs[4 * m + 3] = t4.w;
        }
#pragma unroll
        for (int c = 0; c < 4; c++) p[c] = 0.f;
#pragma unroll
        for (int i = 0; i < 32; i++)
#pragma unroll
            for (int c = 0; c < 4; c++) p[c] = fmaf(hs[i][c], qs[i], p[c]);
#pragma unroll
        for (int c = 0; c < 4; c++) {
            p[c] += __shfl_xor_sync(0xffffffffu, p[c], 1);
            p[c] += __shfl_xor_sync(0xffffffffu, p[c], 2);
            p[c] += __shfl_xor_sync(0xffffffffu, p[c], 4);
        }
        if (j == 0) {
            const float fs = S * 0.0625f;   // 256^-0.5
            float4 o4;
            o4.x = p[0] * fs; o4.y = p[1] * fs; o4.z = p[2] * fs; o4.w = p[3] * fs;
            *(float4*)(d_omid + tb * VAL_DIM + h * VV + vbase + s4) = o4;
        }
    }
}

// ------------- gated RMSNorm over V=512 -> bf16 hi/lo ------------------------
__global__ void __launch_bounds__(256) rmsgate_kernel(const float* __restrict__ wnorm) {
    int warp = (blockIdx.x * blockDim.x + threadIdx.x) >> 5;  // row = (b,t,h)
    int l = threadIdx.x & 31;
    const float* row = d_omid + (size_t)warp * VV;
    const float* gr = d_gatebuf + (size_t)warp * VV;
    float vr[16];
    float s = 0.f;
#pragma unroll
    for (int i = 0; i < 16; i++) {
        vr[i] = row[l + 32 * i];
        s = fmaf(vr[i], vr[i], s);
    }
#pragma unroll
    for (int off = 16; off > 0; off >>= 1) s += __shfl_xor_sync(0xffffffffu, s, off);
    float rinv = rsqrtf(s * (1.f / (float)VV) + 1e-5f);
#pragma unroll
    for (int i = 0; i < 16; i++) {
        int idx = l + 32 * i;
        float gv = gr[idx];
        float sig = 1.f / (1.f + expf(-gv));
        float val = vr[i] * rinv * wnorm[idx] * sig;
        __nv_bfloat16 hh = __float2bfloat16(val);
        d_onhi[(size_t)warp * VV + idx] = hh;
        d_onlo[(size_t)warp * VV + idx] = __float2bfloat16(val - __bfloat162float(hh));
    }
}

// ---------------------------------------------------------------------------
extern "C" void kernel_launch(void* const* d_in, const int* in_sizes, int n_in,
                              void* d_out, int out_size) {
    const float* x = (const float*)d_in[0];
    const float* Wq = (const float*)d_in[1];
    const float* Wk = (const float*)d_in[2];
    const float* Wv = (const float*)d_in[3];
    const float* Wb = (const float*)d_in[4];
    const float* Wa = (const float*)d_in[5];
    const float* A_log = (const float*)d_in[6];
    const float* dt_bias = (const float*)d_in[7];
    const float* Wg = (const float*)d_in[8];
    const float* Wo = (const float*)d_in[9];
    const float* o_norm_w = (const float*)d_in[10];
    float* out = (float*)d_out;

    __nv_bfloat16 *xhi, *xlo, *wqhi, *wqlo, *wkhi, *wklo, *wvhi, *wvlo,
                  *wghi, *wglo, *wohi, *wolo, *onhi, *onlo;
    cudaGetSymbolAddress((void**)&xhi, d_xhi);   cudaGetSymbolAddress((void**)&xlo, d_xlo);
    cudaGetSymbolAddress((void**)&wqhi, d_wqhi); cudaGetSymbolAddress((void**)&wqlo, d_wqlo);
    cudaGetSymbolAddress((void**)&wkhi, d_wkhi); cudaGetSymbolAddress((void**)&wklo, d_wklo);
    cudaGetSymbolAddress((void**)&wvhi, d_wvhi); cudaGetSymbolAddress((void**)&wvlo, d_wvlo);
    cudaGetSymbolAddress((void**)&wghi, d_wghi); cudaGetSymbolAddress((void**)&wglo, d_wglo);
    cudaGetSymbolAddress((void**)&wohi, d_wohi); cudaGetSymbolAddress((void**)&wolo, d_wolo);
    cudaGetSymbolAddress((void**)&onhi, d_onhi); cudaGetSymbolAddress((void**)&onlo, d_onlo);

    cudaFuncSetAttribute(qkvg_gemm, cudaFuncAttributeMaxDynamicSharedMemorySize, GEMM_SMEM);
    cudaFuncSetAttribute(gemm_out, cudaFuncAttributeMaxDynamicSharedMemorySize, GEMM_SMEM);

    // fp32 -> bf16 hi/lo splits
    auto split = [&](const float* src, __nv_bfloat16* hi, __nv_bfloat16* lo, int n) {
        int n4 = n / 4;
        split_bf16<<<(n4 + 255) / 256, 256>>>((const float4*)src,
                                              (__nv_bfloat162*)hi, (__nv_bfloat162*)lo, n4);
    };
    split(x, xhi, xlo, NTOK * DD);
    split(Wq, wqhi, wqlo, KEY_DIM * DD);
    split(Wk, wkhi, wklo, KEY_DIM * NHH * DD);
    split(Wv, wvhi, wvlo, VAL_DIM * NHH * DD);
    split(Wg, wghi, wglo, VAL_DIM * DD);
    split(Wo, wohi, wolo, DD * VAL_DIM);

    // beta / g (independent of GEMMs)
    proj_small<<<(NTOK * 18) / 8, 256>>>(x, Wb, Wa, A_log, dt_bias);

    // fused q/k/v/gate projections
    qkvg_gemm<<<dim3(54, 16), 256, GEMM_SMEM>>>();

    // normalize k rows
    knorm_kernel<<<(NTOK * NHH * HH) / 8, 256>>>();

    // sequential recurrence
    recurrence_kernel<<<96, 256>>>();

    // gated RMSNorm -> bf16 hi/lo
    rmsgate_kernel<<<(NTOK * HH) / 8, 256>>>(o_norm_w);

    // output projection
    gemm_out<<<dim3(DD / 256, NTOK / 128), 256, GEMM_SMEM>>>(onhi, onlo, wohi, wolo, out, VAL_DIM, DD);
}